// round 10
// baseline (speedup 1.0000x reference)
#include <cuda_runtime.h>
#include <math.h>
#include <stdint.h>

#define NB 4
#define CC 256
#define LL 4096
#define NH 8
#define HD 32

__device__ float g_peT[(size_t)CC * LL];                 // 4 MB
__device__ float g_qkv[(size_t)NB * LL * 768];           // 50 MB

// ============================ helpers ============================
__device__ __forceinline__ uint32_t f2tf32(float f) {
    uint32_t r;
    asm("cvt.rna.tf32.f32 %0, %1;" : "=r"(r) : "f"(f));
    return r;
}

// D += A(16x8) * B(8x8)^T-ish: m16n8k8 tf32, fp32 accum (baseline HMMA, no tcgen05)
__device__ __forceinline__ void mma_tf32(float c[4], const uint32_t a[4],
                                         const uint32_t b0, const uint32_t b1) {
    asm volatile(
        "mma.sync.aligned.m16n8k8.row.col.f32.tf32.tf32.f32 "
        "{%0,%1,%2,%3}, {%4,%5,%6,%7}, {%8,%9}, {%0,%1,%2,%3};"
        : "+f"(c[0]), "+f"(c[1]), "+f"(c[2]), "+f"(c[3])
        : "r"(a[0]), "r"(a[1]), "r"(a[2]), "r"(a[3]), "r"(b0), "r"(b1));
}

// ---------------------------------------------------------------------------
// Kernel 0: positional encoding, transposed: peT[c][l].
// ---------------------------------------------------------------------------
__global__ void pe_kernel() {
    __shared__ double s_inv;
    const int c = blockIdx.y;
    if (threadIdx.x == 0) {
        double e = (double)((c >> 1) * 2) / 256.0;
        s_inv = pow(10000.0, -e);
    }
    __syncthreads();
    const int l = blockIdx.x * 256 + threadIdx.x;
    double ang = (double)l * s_inv;
    const double TWO_PI = 6.283185307179586476925286766559;
    double k = floor(ang / TWO_PI);
    float r = (float)(ang - k * TWO_PI);
    g_peT[(size_t)c * LL + l] = (c & 1) ? cosf(r) : sinf(r);
}

// ---------------------------------------------------------------------------
// Kernel 1: qkv = (x^T + PE) @ W_qkv   M=16384, K=256, N=768, tf32 mma.sync
// Block 256 thr (8 warps), tile 128(m) x 64(n); warp w owns rows [16w,16w+16).
// ---------------------------------------------------------------------------
#define PA 136   /* AsT row pad (words): bank = 8t+g, conflict-free a-frag LDS */
#define PB 72    /* Bs row pad: bank = 8t+g, conflict-free b-frag LDS */

__global__ __launch_bounds__(256) void qkv_mma(const float* __restrict__ x,
                                               const float* __restrict__ W) {
    __shared__ uint32_t AsT[32 * PA];   // [k-local][m]
    __shared__ uint32_t Bs[32 * PB];    // [k-local][n]

    const int m0 = blockIdx.x * 128, j0 = blockIdx.y * 64;
    const int n  = m0 >> 12;
    const int l0 = m0 & (LL - 1);
    const int tid = threadIdx.x, w = tid >> 5, lane = tid & 31;
    const int g = lane >> 2, t = lane & 3;
    const float* xb = x + (size_t)n * CC * LL;

    float Cv[8][4];
#pragma unroll
    for (int nb = 0; nb < 8; nb++)
#pragma unroll
        for (int i = 0; i < 4; i++) Cv[nb][i] = 0.0f;

    const int ac = tid >> 3, alq = (tid & 7) * 16;   // A staging: 16 floats along l
    const int bk = tid >> 3, bj8 = (tid & 7) * 8;    // B staging: 8 floats along n

    for (int kc = 0; kc < 256; kc += 32) {
        __syncthreads();
        {
            const float* xr = xb + (size_t)(kc + ac) * LL + l0 + alq;
            const float* pr = g_peT + (size_t)(kc + ac) * LL + l0 + alq;
            uint32_t* ar = AsT + ac * PA + alq;
#pragma unroll
            for (int j = 0; j < 4; j++) {
                float4 xv = *(const float4*)(xr + 4 * j);
                float4 pv = *(const float4*)(pr + 4 * j);
                uint4 o;
                o.x = f2tf32(xv.x + pv.x); o.y = f2tf32(xv.y + pv.y);
                o.z = f2tf32(xv.z + pv.z); o.w = f2tf32(xv.w + pv.w);
                *(uint4*)(ar + 4 * j) = o;
            }
            const float* wr = W + (size_t)(kc + bk) * 768 + j0 + bj8;
            uint32_t* br = Bs + bk * PB + bj8;
#pragma unroll
            for (int j = 0; j < 2; j++) {
                float4 wv = *(const float4*)(wr + 4 * j);
                uint4 o;
                o.x = f2tf32(wv.x); o.y = f2tf32(wv.y);
                o.z = f2tf32(wv.z); o.w = f2tf32(wv.w);
                *(uint4*)(br + 4 * j) = o;
            }
        }
        __syncthreads();

        const int wr0 = w * 16;
#pragma unroll
        for (int s = 0; s < 4; s++) {
            uint32_t a[4];
            a[0] = AsT[(s * 8 + t) * PA + wr0 + g];
            a[1] = AsT[(s * 8 + t) * PA + wr0 + g + 8];
            a[2] = AsT[(s * 8 + t + 4) * PA + wr0 + g];
            a[3] = AsT[(s * 8 + t + 4) * PA + wr0 + g + 8];
#pragma unroll
            for (int nbk = 0; nbk < 8; nbk++) {
                uint32_t b0 = Bs[(s * 8 + t) * PB + nbk * 8 + g];
                uint32_t b1 = Bs[(s * 8 + t + 4) * PB + nbk * 8 + g];
                mma_tf32(Cv[nbk], a, b0, b1);
            }
        }
    }

#pragma unroll
    for (int nbk = 0; nbk < 8; nbk++) {
        size_t row = (size_t)m0 + w * 16 + g;
        int col = j0 + nbk * 8 + 2 * t;
        *(float2*)(g_qkv + row * 768 + col) = make_float2(Cv[nbk][0], Cv[nbk][1]);
        *(float2*)(g_qkv + (row + 8) * 768 + col) = make_float2(Cv[nbk][2], Cv[nbk][3]);
    }
}

// ---------------------------------------------------------------------------
// Kernel 2: tf32 mma.sync flash attention, no-max softmax, O in registers.
// grid(32 qtiles, 8 h, 4 n), 256 thr (8 warps); warp owns 16 q-rows; BK=64.
// ---------------------------------------------------------------------------
#define PK 36   /* Ks pad: b-frag bank = 4g+t, conflict-free */
#define PV 40   /* Vs pad: b-frag bank = 8t+g, conflict-free */

__global__ __launch_bounds__(256) void attn_mma(float* __restrict__ out) {
    __shared__ uint32_t Ks[64 * PK];   // [kv][d] tf32
    __shared__ uint32_t Vs[64 * PV];   // [kv][d] tf32

    const int qt = blockIdx.x, h = blockIdx.y, n = blockIdx.z;
    const int tid = threadIdx.x, w = tid >> 5, lane = tid & 31;
    const int g = lane >> 2, t = lane & 3;
    const float* bptr = g_qkv + (size_t)n * LL * 768;
    const float* Qp = bptr + h * HD;
    const float* Kp = bptr + 256 + h * HD;
    const float* Vp = bptr + 512 + h * HD;
    const int l0 = qt * 128;
    const float scale = 0.17677669529663688f;   // 1/sqrt(32)

    // Q fragments held in registers for the whole CTA lifetime (one-time LDG)
    uint32_t qa[4][4];
    {
        const int r0 = l0 + w * 16 + g, r1 = r0 + 8;
#pragma unroll
        for (int s = 0; s < 4; s++) {
            qa[s][0] = f2tf32(__ldg(Qp + (size_t)r0 * 768 + s * 8 + t) * scale);
            qa[s][1] = f2tf32(__ldg(Qp + (size_t)r1 * 768 + s * 8 + t) * scale);
            qa[s][2] = f2tf32(__ldg(Qp + (size_t)r0 * 768 + s * 8 + t + 4) * scale);
            qa[s][3] = f2tf32(__ldg(Qp + (size_t)r1 * 768 + s * 8 + t + 4) * scale);
        }
    }

    float O[4][4];
#pragma unroll
    for (int nb2 = 0; nb2 < 4; nb2++)
#pragma unroll
        for (int i = 0; i < 4; i++) O[nb2][i] = 0.0f;
    float lsum0 = 0.0f, lsum1 = 0.0f;   // row g / row g+8 partial softmax sums

    const int sr = tid >> 2, sd = (tid & 3) * 8;   // staging: row, d-offset
    const int base4 = lane & ~3;                   // lane group base for shfl
    const int srcA = base4 + (t >> 1);
    const int srcB = base4 + 2 + (t >> 1);
    const bool odd = (t & 1);

    for (int kt = 0; kt < 64; kt++) {
        const int c0 = kt * 64;
        __syncthreads();
        // Stage K, V tiles (64 x 32) as tf32
        {
            const float* kr = Kp + (size_t)(c0 + sr) * 768 + sd;
            const float* vr = Vp + (size_t)(c0 + sr) * 768 + sd;
            float4 k0 = *(const float4*)(kr), k1 = *(const float4*)(kr + 4);
            float4 v0 = *(const float4*)(vr), v1 = *(const float4*)(vr + 4);
            uint32_t* kw = Ks + sr * PK + sd;
            uint32_t* vw = Vs + sr * PV + sd;
            *(uint2*)(kw + 0) = make_uint2(f2tf32(k0.x), f2tf32(k0.y));
            *(uint2*)(kw + 2) = make_uint2(f2tf32(k0.z), f2tf32(k0.w));
            *(uint2*)(kw + 4) = make_uint2(f2tf32(k1.x), f2tf32(k1.y));
            *(uint2*)(kw + 6) = make_uint2(f2tf32(k1.z), f2tf32(k1.w));
            *(uint2*)(vw + 0) = make_uint2(f2tf32(v0.x), f2tf32(v0.y));
            *(uint2*)(vw + 2) = make_uint2(f2tf32(v0.z), f2tf32(v0.w));
            *(uint2*)(vw + 4) = make_uint2(f2tf32(v1.x), f2tf32(v1.y));
            *(uint2*)(vw + 6) = make_uint2(f2tf32(v1.z), f2tf32(v1.w));
        }
        __syncthreads();

        // S = Q K^T : 8 n-blocks of 8 kv, k-dim = d (4 steps of 8)
        float Cv[8][4];
#pragma unroll
        for (int nbk = 0; nbk < 8; nbk++)
#pragma unroll
            for (int i = 0; i < 4; i++) Cv[nbk][i] = 0.0f;
#pragma unroll
        for (int s = 0; s < 4; s++) {
#pragma unroll
            for (int nbk = 0; nbk < 8; nbk++) {
                uint32_t b0 = Ks[(nbk * 8 + g) * PK + s * 8 + t];
                uint32_t b1 = Ks[(nbk * 8 + g) * PK + s * 8 + t + 4];
                mma_tf32(Cv[nbk], qa[s], b0, b1);
            }
        }

        // Softmax without max-subtraction; P kept in registers (tf32 patterns).
        uint32_t P[8][4];
#pragma unroll
        for (int nbk = 0; nbk < 8; nbk++) {
            uint32_t p0 = f2tf32(__expf(Cv[nbk][0]));
            uint32_t p1 = f2tf32(__expf(Cv[nbk][1]));
            uint32_t p2 = f2tf32(__expf(Cv[nbk][2]));
            uint32_t p3 = f2tf32(__expf(Cv[nbk][3]));
            // sum the tf32-rounded values so numerator/denominator match
            lsum0 += __uint_as_float(p0) + __uint_as_float(p1);
            lsum1 += __uint_as_float(p2) + __uint_as_float(p3);
            P[nbk][0] = p0; P[nbk][1] = p1; P[nbk][2] = p2; P[nbk][3] = p3;
        }

        // O += P V : k-dim = kv (8 steps of 8, each = one n-block of S)
#pragma unroll
        for (int s = 0; s < 8; s++) {
            // C-fragment -> A-fragment permutation via shfl (cols {2t,2t+1} -> {t,t+4})
            uint32_t a[4];
            uint32_t u0 = __shfl_sync(0xffffffffu, P[s][0], srcA);
            uint32_t u1 = __shfl_sync(0xffffffffu, P[s][1], srcA);
            a[0] = odd ? u1 : u0;
            uint32_t w0 = __shfl_sync(0xffffffffu, P[s][0], srcB);
            uint32_t w1 = __shfl_sync(0xffffffffu, P[s][1], srcB);
            a[2] = odd ? w1 : w0;
            uint32_t x0 = __shfl_sync(0xffffffffu, P[s][2], srcA);
            uint32_t x1 = __shfl_sync(0xffffffffu, P[s][3], srcA);
            a[1] = odd ? x1 : x0;
            uint32_t y0 = __shfl_sync(0xffffffffu, P[s][2], srcB);
            uint32_t y1 = __shfl_sync(0xffffffffu, P[s][3], srcB);
            a[3] = odd ? y1 : y0;
#pragma unroll
            for (int nb2 = 0; nb2 < 4; nb2++) {
                uint32_t b0 = Vs[(s * 8 + t) * PV + nb2 * 8 + g];
                uint32_t b1 = Vs[(s * 8 + t + 4) * PV + nb2 * 8 + g];
                mma_tf32(O[nb2], a, b0, b1);
            }
        }
    }

    // Row-sum reduction across the 4 lanes of each row group
    lsum0 += __shfl_xor_sync(0xffffffffu, lsum0, 1);
    lsum0 += __shfl_xor_sync(0xffffffffu, lsum0, 2);
    lsum1 += __shfl_xor_sync(0xffffffffu, lsum1, 1);
    lsum1 += __shfl_xor_sync(0xffffffffu, lsum1, 2);
    const float inv0 = 1.0f / lsum0, inv1 = 1.0f / lsum1;

    // Epilogue: out[(n*C + h*32 + d) * L + q]
    const int q0 = l0 + w * 16 + g;
    float* ob = out + ((size_t)(n * CC + h * HD)) * LL;
#pragma unroll
    for (int nb2 = 0; nb2 < 4; nb2++) {
        int d = nb2 * 8 + 2 * t;
        ob[(size_t)d * LL + q0]           = O[nb2][0] * inv0;
        ob[(size_t)(d + 1) * LL + q0]     = O[nb2][1] * inv0;
        ob[(size_t)d * LL + q0 + 8]       = O[nb2][2] * inv1;
        ob[(size_t)(d + 1) * LL + q0 + 8] = O[nb2][3] * inv1;
    }
}

// ---------------------------------------------------------------------------
extern "C" void kernel_launch(void* const* d_in, const int* in_sizes, int n_in,
                              void* d_out, int out_size) {
    const float* x = (const float*)d_in[0];   // (4,256,64,64) fp32
    const float* W = (const float*)d_in[1];   // (256,768) fp32
    float* out = (float*)d_out;               // (4,256,64,64) fp32

    pe_kernel<<<dim3(16, 256), 256>>>();
    qkv_mma<<<dim3(128, 12), 256>>>(x, W);
    attn_mma<<<dim3(32, NH, NB), 256>>>(out);
}

// round 11
// speedup vs baseline: 2.3978x; 2.3978x over previous
#include <cuda_runtime.h>
#include <cuda_fp16.h>
#include <math.h>
#include <stdint.h>

#define NB 4
#define CC 256
#define LL 4096
#define NH 8
#define HD 32

__device__ float  g_peT[(size_t)CC * LL];          // 4 MB fp32 PE table
__device__ __half g_qkv[(size_t)NB * LL * 768];    // 25 MB fp16 activations

// ============================ helpers ============================
__device__ __forceinline__ uint32_t smem_u32(const void* p) {
    return (uint32_t)__cvta_generic_to_shared(p);
}
__device__ __forceinline__ void ldsm_x4(uint32_t r[4], uint32_t a) {
    asm volatile("ldmatrix.sync.aligned.m8n8.x4.shared.b16 {%0,%1,%2,%3}, [%4];"
                 : "=r"(r[0]), "=r"(r[1]), "=r"(r[2]), "=r"(r[3]) : "r"(a));
}
__device__ __forceinline__ void ldsm_x4t(uint32_t r[4], uint32_t a) {
    asm volatile("ldmatrix.sync.aligned.m8n8.x4.trans.shared.b16 {%0,%1,%2,%3}, [%4];"
                 : "=r"(r[0]), "=r"(r[1]), "=r"(r[2]), "=r"(r[3]) : "r"(a));
}
__device__ __forceinline__ void mma16816(float c[4], const uint32_t a[4],
                                         uint32_t b0, uint32_t b1) {
    asm volatile(
        "mma.sync.aligned.m16n8k16.row.col.f32.f16.f16.f32 "
        "{%0,%1,%2,%3},{%4,%5,%6,%7},{%8,%9},{%0,%1,%2,%3};"
        : "+f"(c[0]), "+f"(c[1]), "+f"(c[2]), "+f"(c[3])
        : "r"(a[0]), "r"(a[1]), "r"(a[2]), "r"(a[3]), "r"(b0), "r"(b1));
}
__device__ __forceinline__ uint32_t packh2(float lo, float hi) {   // lo -> low 16 bits
    uint32_t d;
    asm("cvt.rn.f16x2.f32 %0, %1, %2;" : "=r"(d) : "f"(hi), "f"(lo));
    return d;
}
__device__ __forceinline__ float ex2f(float x) {
    float r;
    asm("ex2.approx.f32 %0, %1;" : "=f"(r) : "f"(x));
    return r;
}

// ---------------------------------------------------------------------------
// Kernel 0: positional encoding peT[c][l] — fp32 fast path.
// ---------------------------------------------------------------------------
__global__ void pe_kernel() {
    __shared__ float s_phase, s_inv;
    const int c = blockIdx.y;
    const int l0 = blockIdx.x * 256;
    if (threadIdx.x == 0) {
        double e = (double)((c >> 1) * 2) / 256.0;
        double inv = pow(10000.0, -e);
        double ang0 = (double)l0 * inv;
        const double TP = 6.283185307179586476925286766559;
        s_phase = (float)(ang0 - floor(ang0 / TP) * TP);
        s_inv = (float)inv;
    }
    __syncthreads();
    float ang = fmaf((float)threadIdx.x, s_inv, s_phase);   // <= 2pi + 256
    const float I2P   = 0.15915494309189535f;
    const float P2_HI = 6.2831854820251465f;
    const float P2_LO = -1.7484556e-7f;
    float k = rintf(ang * I2P);
    float r = fmaf(-k, P2_HI, ang);
    r = fmaf(-k, P2_LO, r);
    g_peT[(size_t)c * LL + l0 + threadIdx.x] = (c & 1) ? __cosf(r) : __sinf(r);
}

// ---------------------------------------------------------------------------
// Kernel 1: qkv(fp16) = (x^T + PE) @ W_qkv   M=16384 K=256 N=768, fp16 HMMA
// Block 256 thr, tile 128(m) x 128(n); warp w -> m rows [16w,16w+16).
// As[k=32][m=128], Bs[k=32][n=128] halves, pitch 136 (bank grp (k+c)%8).
// ---------------------------------------------------------------------------
#define QP 136
__global__ __launch_bounds__(256) void qkv_mma(const float* __restrict__ x,
                                               const float* __restrict__ W) {
    __shared__ __half As[32 * QP];
    __shared__ __half Bs[32 * QP];

    const int m0 = blockIdx.x * 128, j0 = blockIdx.y * 128;
    const int nb_ = m0 >> 12;
    const int l0 = m0 & (LL - 1);
    const int tid = threadIdx.x, w = tid >> 5, lane = tid & 31;
    const int g = lane >> 2, t = lane & 3;
    const float* xb = x + (size_t)nb_ * CC * LL;

    float Cv[16][4];
#pragma unroll
    for (int i = 0; i < 16; i++)
#pragma unroll
        for (int j = 0; j < 4; j++) Cv[i][j] = 0.0f;

    const uint32_t as_b = smem_u32(As), bs_b = smem_u32(Bs);
    // staging: row k = tid>>3 (0..31), 16 elems at offset (tid&7)*16
    const int stk = tid >> 3, stoff = (tid & 7) * 16;
    // ldsm lane geometry
    const int arow = ((lane >> 4) & 1) * 8 + (lane & 7);
    const int acol = w * 16 + ((lane >> 3) & 1) * 8;
    const int brow = ((lane >> 3) & 1) * 8 + (lane & 7);
    const int bcpar = ((lane >> 4) & 1) * 8;

    for (int kc = 0; kc < 256; kc += 32) {
        __syncthreads();
        {
            const float* xr = xb + (size_t)(kc + stk) * LL + l0 + stoff;
            const float* pr = g_peT + (size_t)(kc + stk) * LL + l0 + stoff;
            const float* wr = W + (size_t)(kc + stk) * 768 + j0 + stoff;
            uint32_t abuf[8], bbuf[8];
#pragma unroll
            for (int j = 0; j < 4; j++) {
                float4 xv = *(const float4*)(xr + 4 * j);
                float4 pv = *(const float4*)(pr + 4 * j);
                float4 wv = *(const float4*)(wr + 4 * j);
                abuf[2 * j]     = packh2(xv.x + pv.x, xv.y + pv.y);
                abuf[2 * j + 1] = packh2(xv.z + pv.z, xv.w + pv.w);
                bbuf[2 * j]     = packh2(wv.x, wv.y);
                bbuf[2 * j + 1] = packh2(wv.z, wv.w);
            }
            uint32_t* ar = (uint32_t*)(As + stk * QP + stoff);
            uint32_t* br = (uint32_t*)(Bs + stk * QP + stoff);
            *(uint4*)ar       = make_uint4(abuf[0], abuf[1], abuf[2], abuf[3]);
            *(uint4*)(ar + 4) = make_uint4(abuf[4], abuf[5], abuf[6], abuf[7]);
            *(uint4*)br       = make_uint4(bbuf[0], bbuf[1], bbuf[2], bbuf[3]);
            *(uint4*)(br + 4) = make_uint4(bbuf[4], bbuf[5], bbuf[6], bbuf[7]);
        }
        __syncthreads();

#pragma unroll
        for (int s = 0; s < 2; s++) {
            uint32_t a[4];
            ldsm_x4t(a, as_b + ((16 * s + arow) * QP + acol) * 2);
#pragma unroll
            for (int nbp = 0; nbp < 8; nbp++) {
                uint32_t b[4];
                ldsm_x4t(b, bs_b + ((16 * s + brow) * QP + nbp * 16 + bcpar) * 2);
                mma16816(Cv[2 * nbp], a, b[0], b[1]);
                mma16816(Cv[2 * nbp + 1], a, b[2], b[3]);
            }
        }
    }

    size_t row0 = (size_t)m0 + w * 16 + g;
    uint32_t* q32 = (uint32_t*)g_qkv;
#pragma unroll
    for (int nbk = 0; nbk < 16; nbk++) {
        int col = j0 + nbk * 8 + 2 * t;
        q32[(row0 * 768 + col) >> 1]         = packh2(Cv[nbk][0], Cv[nbk][1]);
        q32[((row0 + 8) * 768 + col) >> 1]   = packh2(Cv[nbk][2], Cv[nbk][3]);
    }
}

// ---------------------------------------------------------------------------
// Kernel 2: fp16 HMMA flash attention. No-max base-2 softmax; P identity
// C->A fragment reuse; lsum via ones-column MMA. grid(32,8,4), 256 thr.
// Ks/Vs: [kv=64][d=32] halves, pitch 40 (bank grp (5kv+c)%8 is a permutation).
// ---------------------------------------------------------------------------
#define PKV 40
__global__ __launch_bounds__(256) void attn_mma(float* __restrict__ out) {
    __shared__ __half Ks[64 * PKV];   // 5 KB
    __shared__ __half Vs[64 * PKV];   // 5 KB

    const int qt = blockIdx.x, h = blockIdx.y, n = blockIdx.z;
    const int tid = threadIdx.x, w = tid >> 5, lane = tid & 31;
    const int g = lane >> 2, t = lane & 3;
    const __half* bptr = g_qkv + (size_t)n * LL * 768;
    const __half* Qp = bptr + h * HD;
    const __half* Kp = bptr + 256 + h * HD;
    const __half* Vp = bptr + 512 + h * HD;
    const int l0 = qt * 128;
    const float scale = 0.17677669529663688f * 1.4426950408889634f; // 1/sqrt(32)*log2e

    // Q fragments (scaled in fp32, repacked) — resident for whole kernel
    uint32_t qa[2][4];
    {
        const size_t r0 = (size_t)(l0 + w * 16 + g) * 768;
        const size_t r1 = r0 + 8 * 768;
        const uint32_t* q32 = (const uint32_t*)Qp;
#pragma unroll
        for (int s = 0; s < 2; s++)
#pragma unroll
            for (int i = 0; i < 4; i++) {
                size_t rr = (i & 1) ? r1 : r0;
                int d = 16 * s + ((i >> 1) ? 8 : 0) + 2 * t;
                uint32_t pk = __ldg(q32 + ((rr + d) >> 1));
                __half2 hv = *(__half2*)&pk;
                qa[s][i] = packh2(__low2float(hv) * scale, __high2float(hv) * scale);
            }
    }

    float O[4][4], Osum[4];
#pragma unroll
    for (int i = 0; i < 4; i++) {
        Osum[i] = 0.0f;
#pragma unroll
        for (int j = 0; j < 4; j++) O[i][j] = 0.0f;
    }
    const uint32_t ones = (lane < 4) ? 0x3C003C00u : 0u;   // B col 0 = 1

    const uint32_t ks_b = smem_u32(Ks), vs_b = smem_u32(Vs);
    // ldsm lane geometry
    const int krow = ((lane >> 4) & 1) * 8 + (lane & 7);   // K (non-trans)
    const int kcp  = ((lane >> 3) & 1) * 8;
    const int vrow = ((lane >> 3) & 1) * 8 + (lane & 7);   // V (trans)
    const int vcp  = ((lane >> 4) & 1) * 8;
    // staging: row sr, 8-half chunk sc
    const int sr = tid >> 2, sc = tid & 3;

    for (int kt = 0; kt < 64; kt++) {
        const int c0 = kt * 64;
        __syncthreads();
        {
            uint4 kd = *(const uint4*)(Kp + (size_t)(c0 + sr) * 768 + sc * 8);
            uint4 vd = *(const uint4*)(Vp + (size_t)(c0 + sr) * 768 + sc * 8);
            *(uint4*)(Ks + sr * PKV + sc * 8) = kd;
            *(uint4*)(Vs + sr * PKV + sc * 8) = vd;
        }
        __syncthreads();

        // S = Q K^T (log2 domain): 8 n-blocks x 2 k-chunks
        float Cv[8][4];
#pragma unroll
        for (int i = 0; i < 8; i++)
#pragma unroll
            for (int j = 0; j < 4; j++) Cv[i][j] = 0.0f;
#pragma unroll
        for (int s = 0; s < 2; s++)
#pragma unroll
            for (int nbp = 0; nbp < 4; nbp++) {
                uint32_t b[4];
                ldsm_x4(b, ks_b + ((nbp * 16 + krow) * PKV + s * 16 + kcp) * 2);
                mma16816(Cv[2 * nbp], qa[s], b[0], b[1]);
                mma16816(Cv[2 * nbp + 1], qa[s], b[2], b[3]);
            }

        // P = 2^S, packed half2 — identity C->A fragment mapping
        uint32_t P[8][2];
#pragma unroll
        for (int i = 0; i < 8; i++) {
            P[i][0] = packh2(ex2f(Cv[i][0]), ex2f(Cv[i][1]));
            P[i][1] = packh2(ex2f(Cv[i][2]), ex2f(Cv[i][3]));
        }

        // O += P V ; Osum += P * ones
#pragma unroll
        for (int s = 0; s < 4; s++) {
            uint32_t a[4] = {P[2 * s][0], P[2 * s][1], P[2 * s + 1][0], P[2 * s + 1][1]};
#pragma unroll
            for (int dp = 0; dp < 2; dp++) {
                uint32_t b[4];
                ldsm_x4t(b, vs_b + ((16 * s + vrow) * PKV + dp * 16 + vcp) * 2);
                mma16816(O[2 * dp], a, b[0], b[1]);
                mma16816(O[2 * dp + 1], a, b[2], b[3]);
            }
            mma16816(Osum, a, ones, ones);
        }
    }

    // row sums live in lanes t=0 (col 0 of Osum)
    float lsum0 = __shfl_sync(0xffffffffu, Osum[0], lane & 28);
    float lsum1 = __shfl_sync(0xffffffffu, Osum[2], lane & 28);
    const float inv0 = 1.0f / lsum0, inv1 = 1.0f / lsum1;

    // Epilogue: out[(n*C + h*32 + d) * L + q]
    const int q0 = l0 + w * 16 + g;
    float* ob = out + ((size_t)(n * CC + h * HD)) * LL;
#pragma unroll
    for (int nb2 = 0; nb2 < 4; nb2++) {
        int d = nb2 * 8 + 2 * t;
        ob[(size_t)d * LL + q0]           = O[nb2][0] * inv0;
        ob[(size_t)(d + 1) * LL + q0]     = O[nb2][1] * inv0;
        ob[(size_t)d * LL + q0 + 8]       = O[nb2][2] * inv1;
        ob[(size_t)(d + 1) * LL + q0 + 8] = O[nb2][3] * inv1;
    }
}

// ---------------------------------------------------------------------------
extern "C" void kernel_launch(void* const* d_in, const int* in_sizes, int n_in,
                              void* d_out, int out_size) {
    const float* x = (const float*)d_in[0];   // (4,256,64,64) fp32
    const float* W = (const float*)d_in[1];   // (256,768) fp32
    float* out = (float*)d_out;               // (4,256,64,64) fp32

    pe_kernel<<<dim3(16, 256), 256>>>();
    qkv_mma<<<dim3(128, 6), 256>>>(x, W);
    attn_mma<<<dim3(32, NH, NB), 256>>>(out);
}

// round 14
// speedup vs baseline: 2.7190x; 1.1340x over previous
#include <cuda_runtime.h>
#include <cuda_fp16.h>
#include <math.h>
#include <stdint.h>

#define NB 4
#define CC 256
#define LL 4096
#define NH 8
#define HD 32

__device__ float  g_peT[(size_t)CC * LL];          // 4 MB fp32 PE table
__device__ __half g_qkv[(size_t)NB * LL * 768];    // 25 MB fp16 activations

// ============================ helpers ============================
__device__ __forceinline__ uint32_t smem_u32(const void* p) {
    return (uint32_t)__cvta_generic_to_shared(p);
}
__device__ __forceinline__ void ldsm_x4(uint32_t r[4], uint32_t a) {
    asm volatile("ldmatrix.sync.aligned.m8n8.x4.shared.b16 {%0,%1,%2,%3}, [%4];"
                 : "=r"(r[0]), "=r"(r[1]), "=r"(r[2]), "=r"(r[3]) : "r"(a));
}
__device__ __forceinline__ void ldsm_x4t(uint32_t r[4], uint32_t a) {
    asm volatile("ldmatrix.sync.aligned.m8n8.x4.trans.shared.b16 {%0,%1,%2,%3}, [%4];"
                 : "=r"(r[0]), "=r"(r[1]), "=r"(r[2]), "=r"(r[3]) : "r"(a));
}
__device__ __forceinline__ void mma16816(float c[4], const uint32_t a[4],
                                         uint32_t b0, uint32_t b1) {
    asm volatile(
        "mma.sync.aligned.m16n8k16.row.col.f32.f16.f16.f32 "
        "{%0,%1,%2,%3},{%4,%5,%6,%7},{%8,%9},{%0,%1,%2,%3};"
        : "+f"(c[0]), "+f"(c[1]), "+f"(c[2]), "+f"(c[3])
        : "r"(a[0]), "r"(a[1]), "r"(a[2]), "r"(a[3]), "r"(b0), "r"(b1));
}
__device__ __forceinline__ uint32_t packh2(float lo, float hi) {   // lo -> low 16 bits
    uint32_t d;
    asm("cvt.rn.f16x2.f32 %0, %1, %2;" : "=r"(d) : "f"(hi), "f"(lo));
    return d;
}
__device__ __forceinline__ uint32_t ex2h2(uint32_t x) {            // 2^x on half2
    uint32_t d;
    asm("ex2.approx.f16x2 %0, %1;" : "=r"(d) : "r"(x));
    return d;
}
#define CP16(dst, src) \
    asm volatile("cp.async.cg.shared.global [%0], [%1], 16;" :: "r"(dst), "l"(src))
#define CP_COMMIT() asm volatile("cp.async.commit_group;" ::: "memory")
#define CP_WAIT(n)  asm volatile("cp.async.wait_group %0;" :: "n"(n) : "memory")

// ---------------------------------------------------------------------------
// Kernel 0: positional encoding peT[c][l]. One block per channel: the single
// expensive double pow is amortized over 4096 elements (was once per 256).
// ---------------------------------------------------------------------------
__global__ void pe_kernel() {
    __shared__ double s_inv;
    __shared__ float s_phase[16];
    const int c = blockIdx.x;
    const int tid = threadIdx.x;
    if (tid == 0) s_inv = pow(10000.0, -(double)((c >> 1) * 2) / 256.0);
    __syncthreads();
    if (tid < 16) {
        double a0 = (double)(tid * 256) * s_inv;
        const double TP = 6.283185307179586476925286766559;
        s_phase[tid] = (float)(a0 - floor(a0 / TP) * TP);
    }
    const float invf = (float)s_inv;
    __syncthreads();
    float* dst = g_peT + (size_t)c * LL;
    const bool odd = c & 1;
    const float I2P   = 0.15915494309189535f;
    const float P2_HI = 6.2831854820251465f;
    const float P2_LO = -1.7484556e-7f;
#pragma unroll 4
    for (int j = 0; j < 16; j++) {
        float ang = fmaf((float)tid, invf, s_phase[j]);   // <= ~262 rad
        float k = rintf(ang * I2P);
        float r = fmaf(-k, P2_HI, ang);
        r = fmaf(-k, P2_LO, r);
        dst[j * 256 + tid] = odd ? __cosf(r) : __sinf(r);
    }
}

// ---------------------------------------------------------------------------
// Kernel 1: qkv(fp16) = (x^T + PE) @ W_qkv   M=16384 K=256 N=768, fp16 HMMA
// Block 256 thr, tile 128(m) x 128(n); warp w -> m rows [16w,16w+16).
// As[k=32][m=128], Bs[k=32][n=128] halves, pitch 136 (bank grp (k+c)%8).
// ---------------------------------------------------------------------------
#define QP 136
__global__ __launch_bounds__(256) void qkv_mma(const float* __restrict__ x,
                                               const float* __restrict__ W) {
    __shared__ __half As[32 * QP];
    __shared__ __half Bs[32 * QP];

    const int m0 = blockIdx.x * 128, j0 = blockIdx.y * 128;
    const int nb_ = m0 >> 12;
    const int l0 = m0 & (LL - 1);
    const int tid = threadIdx.x, w = tid >> 5, lane = tid & 31;
    const int g = lane >> 2, t = lane & 3;
    const float* xb = x + (size_t)nb_ * CC * LL;

    float Cv[16][4];
#pragma unroll
    for (int i = 0; i < 16; i++)
#pragma unroll
        for (int j = 0; j < 4; j++) Cv[i][j] = 0.0f;

    const uint32_t as_b = smem_u32(As), bs_b = smem_u32(Bs);
    const int stk = tid >> 3, stoff = (tid & 7) * 16;
    const int arow = ((lane >> 4) & 1) * 8 + (lane & 7);
    const int acol = w * 16 + ((lane >> 3) & 1) * 8;
    const int brow = ((lane >> 3) & 1) * 8 + (lane & 7);
    const int bcpar = ((lane >> 4) & 1) * 8;

    for (int kc = 0; kc < 256; kc += 32) {
        __syncthreads();
        {
            const float* xr = xb + (size_t)(kc + stk) * LL + l0 + stoff;
            const float* pr = g_peT + (size_t)(kc + stk) * LL + l0 + stoff;
            const float* wr = W + (size_t)(kc + stk) * 768 + j0 + stoff;
            uint32_t abuf[8], bbuf[8];
#pragma unroll
            for (int j = 0; j < 4; j++) {
                float4 xv = *(const float4*)(xr + 4 * j);
                float4 pv = *(const float4*)(pr + 4 * j);
                float4 wv = *(const float4*)(wr + 4 * j);
                abuf[2 * j]     = packh2(xv.x + pv.x, xv.y + pv.y);
                abuf[2 * j + 1] = packh2(xv.z + pv.z, xv.w + pv.w);
                bbuf[2 * j]     = packh2(wv.x, wv.y);
                bbuf[2 * j + 1] = packh2(wv.z, wv.w);
            }
            uint32_t* ar = (uint32_t*)(As + stk * QP + stoff);
            uint32_t* br = (uint32_t*)(Bs + stk * QP + stoff);
            *(uint4*)ar       = make_uint4(abuf[0], abuf[1], abuf[2], abuf[3]);
            *(uint4*)(ar + 4) = make_uint4(abuf[4], abuf[5], abuf[6], abuf[7]);
            *(uint4*)br       = make_uint4(bbuf[0], bbuf[1], bbuf[2], bbuf[3]);
            *(uint4*)(br + 4) = make_uint4(bbuf[4], bbuf[5], bbuf[6], bbuf[7]);
        }
        __syncthreads();

#pragma unroll
        for (int s = 0; s < 2; s++) {
            uint32_t a[4];
            ldsm_x4t(a, as_b + ((16 * s + arow) * QP + acol) * 2);
#pragma unroll
            for (int nbp = 0; nbp < 8; nbp++) {
                uint32_t b[4];
                ldsm_x4t(b, bs_b + ((16 * s + brow) * QP + nbp * 16 + bcpar) * 2);
                mma16816(Cv[2 * nbp], a, b[0], b[1]);
                mma16816(Cv[2 * nbp + 1], a, b[2], b[3]);
            }
        }
    }

    size_t row0 = (size_t)m0 + w * 16 + g;
    uint32_t* q32 = (uint32_t*)g_qkv;
#pragma unroll
    for (int nbk = 0; nbk < 16; nbk++) {
        int col = j0 + nbk * 8 + 2 * t;
        q32[(row0 * 768 + col) >> 1]       = packh2(Cv[nbk][0], Cv[nbk][1]);
        q32[((row0 + 8) * 768 + col) >> 1] = packh2(Cv[nbk][2], Cv[nbk][3]);
    }
}

// ---------------------------------------------------------------------------
// Kernel 2: fp16 HMMA flash attention. No-max base-2 softmax (ex2.f16x2);
// P identity C->A reuse; lsum via ones-column MMA; cp.async double-buffered
// K/V staging. grid(32,8,4), 256 thr. Pitch 40 halves: bank grp (5kv+c)%8.
// ---------------------------------------------------------------------------
#define PKV 40
#define KVB (64 * PKV * 2)   /* bytes per K/V buffer */
__global__ __launch_bounds__(256, 2) void attn_mma(float* __restrict__ out) {
    __shared__ __half Ks[2][64 * PKV];   // 2 x 5 KB
    __shared__ __half Vs[2][64 * PKV];   // 2 x 5 KB

    const int qt = blockIdx.x, h = blockIdx.y, n = blockIdx.z;
    const int tid = threadIdx.x, w = tid >> 5, lane = tid & 31;
    const int g = lane >> 2, t = lane & 3;
    const __half* bptr = g_qkv + (size_t)n * LL * 768;
    const __half* Qp = bptr + h * HD;
    const __half* Kp = bptr + 256 + h * HD;
    const __half* Vp = bptr + 512 + h * HD;
    const int l0 = qt * 128;
    const float scale = 0.17677669529663688f * 1.4426950408889634f; // 1/sqrt(32)*log2e

    const uint32_t ks_b = smem_u32(Ks), vs_b = smem_u32(Vs);
    const int sr = tid >> 2, sc = tid & 3;   // staging: row, 16B chunk

    // Prologue: stage tile 0 into buffer 0 (async)
    {
        uint32_t off = (sr * PKV + sc * 8) * 2;
        CP16(ks_b + off, Kp + (size_t)sr * 768 + sc * 8);
        CP16(vs_b + off, Vp + (size_t)sr * 768 + sc * 8);
        CP_COMMIT();
    }

    // Q fragments (scaled in fp32, repacked) — resident whole kernel
    uint32_t qa[2][4];
    {
        const size_t r0 = (size_t)(l0 + w * 16 + g) * 768;
        const size_t r1 = r0 + 8 * 768;
        const uint32_t* q32 = (const uint32_t*)Qp;
#pragma unroll
        for (int s = 0; s < 2; s++)
#pragma unroll
            for (int i = 0; i < 4; i++) {
                size_t rr = (i & 1) ? r1 : r0;
                int d = 16 * s + ((i >> 1) ? 8 : 0) + 2 * t;
                uint32_t pk = __ldg(q32 + ((rr + d) >> 1));
                __half2 hv = *(__half2*)&pk;
                qa[s][i] = packh2(__low2float(hv) * scale, __high2float(hv) * scale);
            }
    }

    float O[4][4], Osum[4];
#pragma unroll
    for (int i = 0; i < 4; i++) {
        Osum[i] = 0.0f;
#pragma unroll
        for (int j = 0; j < 4; j++) O[i][j] = 0.0f;
    }
    const uint32_t ones = (lane < 4) ? 0x3C003C00u : 0u;   // B col 0 = 1

    // ldsm lane geometry
    const int krow = ((lane >> 4) & 1) * 8 + (lane & 7);   // K (non-trans)
    const int kcp  = ((lane >> 3) & 1) * 8;
    const int vrow = ((lane >> 3) & 1) * 8 + (lane & 7);   // V (trans)
    const int vcp  = ((lane >> 4) & 1) * 8;

    for (int kt = 0; kt < 64; kt++) {
        const uint32_t cur = (uint32_t)(kt & 1);
        // Issue next tile's loads into the other buffer, then wait for current.
        if (kt < 63) {
            const int c1 = (kt + 1) * 64;
            uint32_t off = (cur ^ 1) * KVB + (sr * PKV + sc * 8) * 2;
            CP16(ks_b + off, Kp + (size_t)(c1 + sr) * 768 + sc * 8);
            CP16(vs_b + off, Vp + (size_t)(c1 + sr) * 768 + sc * 8);
            CP_COMMIT();
            CP_WAIT(1);
        } else {
            CP_WAIT(0);
        }
        __syncthreads();

        const uint32_t kb = ks_b + cur * KVB, vb = vs_b + cur * KVB;

        // S = Q K^T (log2 domain): 8 n-blocks x 2 k-chunks
        float Cv[8][4];
#pragma unroll
        for (int i = 0; i < 8; i++)
#pragma unroll
            for (int j = 0; j < 4; j++) Cv[i][j] = 0.0f;
#pragma unroll
        for (int s = 0; s < 2; s++)
#pragma unroll
            for (int nbp = 0; nbp < 4; nbp++) {
                uint32_t b[4];
                ldsm_x4(b, kb + ((nbp * 16 + krow) * PKV + s * 16 + kcp) * 2);
                mma16816(Cv[2 * nbp], qa[s], b[0], b[1]);
                mma16816(Cv[2 * nbp + 1], qa[s], b[2], b[3]);
            }

        // P = 2^S on half2 pairs (MUFU halved) — identity C->A fragment map
        uint32_t P[8][2];
#pragma unroll
        for (int i = 0; i < 8; i++) {
            P[i][0] = ex2h2(packh2(Cv[i][0], Cv[i][1]));
            P[i][1] = ex2h2(packh2(Cv[i][2], Cv[i][3]));
        }

        // O += P V ; Osum += P * ones
#pragma unroll
        for (int s = 0; s < 4; s++) {
            uint32_t a[4] = {P[2 * s][0], P[2 * s][1], P[2 * s + 1][0], P[2 * s + 1][1]};
#pragma unroll
            for (int dp = 0; dp < 2; dp++) {
                uint32_t b[4];
                ldsm_x4t(b, vb + ((16 * s + vrow) * PKV + dp * 16 + vcp) * 2);
                mma16816(O[2 * dp], a, b[0], b[1]);
                mma16816(O[2 * dp + 1], a, b[2], b[3]);
            }
            mma16816(Osum, a, ones, ones);
        }
        __syncthreads();   // before next iter's cp.async overwrites buf cur^1
    }

    // row sums live in lanes t=0 (col 0 of Osum)
    float lsum0 = __shfl_sync(0xffffffffu, Osum[0], lane & 28);
    float lsum1 = __shfl_sync(0xffffffffu, Osum[2], lane & 28);
    const float inv0 = 1.0f / lsum0, inv1 = 1.0f / lsum1;

    // Epilogue: out[(n*C + h*32 + d) * L + q]
    const int q0 = l0 + w * 16 + g;
    float* ob = out + ((size_t)(n * CC + h * HD)) * LL;
#pragma unroll
    for (int nb2 = 0; nb2 < 4; nb2++) {
        int d = nb2 * 8 + 2 * t;
        ob[(size_t)d * LL + q0]           = O[nb2][0] * inv0;
        ob[(size_t)(d + 1) * LL + q0]     = O[nb2][1] * inv0;
        ob[(size_t)d * LL + q0 + 8]       = O[nb2][2] * inv1;
        ob[(size_t)(d + 1) * LL + q0 + 8] = O[nb2][3] * inv1;
    }
}

// ---------------------------------------------------------------------------
extern "C" void kernel_launch(void* const* d_in, const int* in_sizes, int n_in,
                              void* d_out, int out_size) {
    const float* x = (const float*)d_in[0];   // (4,256,64,64) fp32
    const float* W = (const float*)d_in[1];   // (256,768) fp32
    float* out = (float*)d_out;               // (4,256,64,64) fp32

    pe_kernel<<<256, 256>>>();
    qkv_mma<<<dim3(128, 6), 256>>>(x, W);
    attn_mma<<<dim3(32, NH, NB), 256>>>(out);
}

// round 15
// speedup vs baseline: 3.1838x; 1.1709x over previous
#include <cuda_runtime.h>
#include <cuda_fp16.h>
#include <math.h>
#include <stdint.h>

#define NB 4
#define CC 256
#define LL 4096
#define NH 8
#define HD 32

__device__ float  g_peT[(size_t)CC * LL];          // 4 MB fp32 PE table
__device__ __half g_qkv[(size_t)NB * LL * 768];    // 25 MB fp16 activations
__device__ __half g_Wh[(size_t)CC * 768];          // 384 KB fp16 weights

// ============================ helpers ============================
__device__ __forceinline__ uint32_t smem_u32(const void* p) {
    return (uint32_t)__cvta_generic_to_shared(p);
}
__device__ __forceinline__ void ldsm_x4(uint32_t r[4], uint32_t a) {
    asm volatile("ldmatrix.sync.aligned.m8n8.x4.shared.b16 {%0,%1,%2,%3}, [%4];"
                 : "=r"(r[0]), "=r"(r[1]), "=r"(r[2]), "=r"(r[3]) : "r"(a));
}
__device__ __forceinline__ void ldsm_x4t(uint32_t r[4], uint32_t a) {
    asm volatile("ldmatrix.sync.aligned.m8n8.x4.trans.shared.b16 {%0,%1,%2,%3}, [%4];"
                 : "=r"(r[0]), "=r"(r[1]), "=r"(r[2]), "=r"(r[3]) : "r"(a));
}
__device__ __forceinline__ void mma16816(float c[4], const uint32_t a[4],
                                         uint32_t b0, uint32_t b1) {
    asm volatile(
        "mma.sync.aligned.m16n8k16.row.col.f32.f16.f16.f32 "
        "{%0,%1,%2,%3},{%4,%5,%6,%7},{%8,%9},{%0,%1,%2,%3};"
        : "+f"(c[0]), "+f"(c[1]), "+f"(c[2]), "+f"(c[3])
        : "r"(a[0]), "r"(a[1]), "r"(a[2]), "r"(a[3]), "r"(b0), "r"(b1));
}
__device__ __forceinline__ uint32_t packh2(float lo, float hi) {   // lo -> low 16 bits
    uint32_t d;
    asm("cvt.rn.f16x2.f32 %0, %1, %2;" : "=r"(d) : "f"(hi), "f"(lo));
    return d;
}
__device__ __forceinline__ uint32_t ex2h2(uint32_t x) {            // 2^x on half2
    uint32_t d;
    asm("ex2.approx.f16x2 %0, %1;" : "=r"(d) : "r"(x));
    return d;
}
#define CP16(dst, src) \
    asm volatile("cp.async.cg.shared.global [%0], [%1], 16;" :: "r"(dst), "l"(src))
#define CP_COMMIT() asm volatile("cp.async.commit_group;" ::: "memory")
#define CP_WAIT(n)  asm volatile("cp.async.wait_group %0;" :: "n"(n) : "memory")

// ---------------------------------------------------------------------------
// Kernel 0a: positional encoding peT[c][l] (one block per channel).
// ---------------------------------------------------------------------------
__global__ void pe_kernel() {
    __shared__ double s_inv;
    __shared__ float s_phase[16];
    const int c = blockIdx.x;
    const int tid = threadIdx.x;
    if (tid == 0) s_inv = pow(10000.0, -(double)((c >> 1) * 2) / 256.0);
    __syncthreads();
    if (tid < 16) {
        double a0 = (double)(tid * 256) * s_inv;
        const double TP = 6.283185307179586476925286766559;
        s_phase[tid] = (float)(a0 - floor(a0 / TP) * TP);
    }
    const float invf = (float)s_inv;
    __syncthreads();
    float* dst = g_peT + (size_t)c * LL;
    const bool odd = c & 1;
    const float I2P   = 0.15915494309189535f;
    const float P2_HI = 6.2831854820251465f;
    const float P2_LO = -1.7484556e-7f;
#pragma unroll 4
    for (int j = 0; j < 16; j++) {
        float ang = fmaf((float)tid, invf, s_phase[j]);
        float k = rintf(ang * I2P);
        float r = fmaf(-k, P2_HI, ang);
        r = fmaf(-k, P2_LO, r);
        dst[j * 256 + tid] = odd ? __cosf(r) : __sinf(r);
    }
}

// ---------------------------------------------------------------------------
// Kernel 0b: W fp32 -> fp16 (196608 elems; 96 blocks x 256 thr x 8)
// ---------------------------------------------------------------------------
__global__ void w_conv(const float* __restrict__ W) {
    int i = (blockIdx.x * 256 + threadIdx.x) * 8;
    float4 a = *(const float4*)(W + i);
    float4 b = *(const float4*)(W + i + 4);
    uint4 o;
    o.x = packh2(a.x, a.y); o.y = packh2(a.z, a.w);
    o.z = packh2(b.x, b.y); o.w = packh2(b.z, b.w);
    *(uint4*)((uint32_t*)g_Wh + (i >> 1)) = o;
}

// ---------------------------------------------------------------------------
// Kernel 1: qkv(fp16) = (x^T + PE) @ W_qkv.  A-RESIDENT: full 128(m) x 256(k)
// A tile in smem (x read exactly once); loop 6 j-tiles of 128; B chunks
// cp.async double-buffered from fp16 g_Wh. 256 thr, dynamic smem 87 KB.
// ---------------------------------------------------------------------------
#define QP 136
#define ASZ (256 * QP)            /* halves */
#define BCH (32 * QP)             /* halves per B buffer */
__global__ __launch_bounds__(256) void qkv_mma(const float* __restrict__ x) {
    extern __shared__ __half sm[];
    __half* As = sm;              // [k=256][m=128] pitch QP
    __half* Bs = sm + ASZ;        // [2][k=32][n=128] pitch QP

    const int m0 = blockIdx.x * 128;
    const int nb_ = m0 >> 12;
    const int l0 = m0 & (LL - 1);
    const int tid = threadIdx.x, w = tid >> 5, lane = tid & 31;
    const int g = lane >> 2, t = lane & 3;
    const float* xb = x + (size_t)nb_ * CC * LL;

    const uint32_t as_b = smem_u32(As), bs_b = smem_u32(Bs);
    const int stk = tid >> 3, stoff = (tid & 7) * 16;
    // B staging (cp.async): 512 chunks of 16B; thread e covers e, e+256
    const int brow0 = tid >> 4, bch0 = tid & 15;
    // ldsm lane geometry
    const int arow = ((lane >> 4) & 1) * 8 + (lane & 7);
    const int acol = w * 16 + ((lane >> 3) & 1) * 8;
    const int brow = ((lane >> 3) & 1) * 8 + (lane & 7);
    const int bcpar = ((lane >> 4) & 1) * 8;

    // ---- Stage full A (once): x^T + PE -> fp16 ----
#pragma unroll
    for (int kc = 0; kc < 256; kc += 32) {
        const float* xr = xb + (size_t)(kc + stk) * LL + l0 + stoff;
        const float* pr = g_peT + (size_t)(kc + stk) * LL + l0 + stoff;
        uint32_t abuf[8];
#pragma unroll
        for (int j = 0; j < 4; j++) {
            float4 xv = *(const float4*)(xr + 4 * j);
            float4 pv = *(const float4*)(pr + 4 * j);
            abuf[2 * j]     = packh2(xv.x + pv.x, xv.y + pv.y);
            abuf[2 * j + 1] = packh2(xv.z + pv.z, xv.w + pv.w);
        }
        uint32_t* ar = (uint32_t*)(As + (kc + stk) * QP + stoff);
        *(uint4*)ar       = make_uint4(abuf[0], abuf[1], abuf[2], abuf[3]);
        *(uint4*)(ar + 4) = make_uint4(abuf[4], abuf[5], abuf[6], abuf[7]);
    }
    __syncthreads();

    for (int j = 0; j < 6; j++) {
        const int j0 = j * 128;
        // prologue: B chunk 0 -> buf 0
        {
            uint32_t d0 = bs_b + ((brow0 * QP + bch0 * 8) << 1);
            const __half* s0 = g_Wh + (size_t)brow0 * 768 + j0 + bch0 * 8;
            CP16(d0, s0);
            CP16(d0 + ((16 * QP) << 1), s0 + 16 * 768);
            CP_COMMIT();
        }
        float Cv[16][4];
#pragma unroll
        for (int i = 0; i < 16; i++)
#pragma unroll
            for (int q = 0; q < 4; q++) Cv[i][q] = 0.0f;

        for (int kc8 = 0; kc8 < 8; kc8++) {
            const uint32_t cur = (uint32_t)(kc8 & 1);
            if (kc8 < 7) {
                uint32_t d0 = bs_b + (((cur ^ 1) * BCH + brow0 * QP + bch0 * 8) << 1);
                const __half* s0 = g_Wh + (size_t)((kc8 + 1) * 32 + brow0) * 768 + j0 + bch0 * 8;
                CP16(d0, s0);
                CP16(d0 + ((16 * QP) << 1), s0 + 16 * 768);
                CP_COMMIT();
                CP_WAIT(1);
            } else {
                CP_WAIT(0);
            }
            __syncthreads();
            const uint32_t bb = bs_b + ((cur * BCH) << 1);
#pragma unroll
            for (int s = 0; s < 2; s++) {
                uint32_t a[4];
                ldsm_x4t(a, as_b + (((kc8 * 32 + 16 * s + arow) * QP + acol) << 1));
#pragma unroll
                for (int nbp = 0; nbp < 8; nbp++) {
                    uint32_t b[4];
                    ldsm_x4t(b, bb + (((16 * s + brow) * QP + nbp * 16 + bcpar) << 1));
                    mma16816(Cv[2 * nbp], a, b[0], b[1]);
                    mma16816(Cv[2 * nbp + 1], a, b[2], b[3]);
                }
            }
            __syncthreads();
        }

        size_t row0 = (size_t)m0 + w * 16 + g;
        uint32_t* q32 = (uint32_t*)g_qkv;
#pragma unroll
        for (int nbk = 0; nbk < 16; nbk++) {
            int col = j0 + nbk * 8 + 2 * t;
            q32[(row0 * 768 + col) >> 1]       = packh2(Cv[nbk][0], Cv[nbk][1]);
            q32[((row0 + 8) * 768 + col) >> 1] = packh2(Cv[nbk][2], Cv[nbk][3]);
        }
    }
}

// ---------------------------------------------------------------------------
// Kernel 2: fp16 HMMA flash attention, BQ=256 (32 q-rows/warp, 2 m-blocks
// pipelined). No-max base-2 softmax (ex2.f16x2), identity C->A P reuse,
// lsum via ones-column MMA, cp.async double-buffered K/V. grid(16,8,4).
// ---------------------------------------------------------------------------
#define PKV 40
#define KVB (64 * PKV * 2)   /* bytes per K/V buffer */
__global__ __launch_bounds__(256, 2) void attn_mma(float* __restrict__ out) {
    __shared__ __half Ks[2][64 * PKV];   // 2 x 5 KB
    __shared__ __half Vs[2][64 * PKV];   // 2 x 5 KB

    const int qt = blockIdx.x, h = blockIdx.y, n = blockIdx.z;
    const int tid = threadIdx.x, w = tid >> 5, lane = tid & 31;
    const int g = lane >> 2, t = lane & 3;
    const __half* bptr = g_qkv + (size_t)n * LL * 768;
    const __half* Qp = bptr + h * HD;
    const __half* Kp = bptr + 256 + h * HD;
    const __half* Vp = bptr + 512 + h * HD;
    const int l0 = qt * 256;
    const float scale = 0.17677669529663688f * 1.4426950408889634f; // 1/sqrt(32)*log2e

    const uint32_t ks_b = smem_u32(Ks), vs_b = smem_u32(Vs);
    const int sr = tid >> 2, sc = tid & 3;   // staging: row, 16B chunk

    // Prologue: stage tile 0 into buffer 0
    {
        uint32_t off = (sr * PKV + sc * 8) * 2;
        CP16(ks_b + off, Kp + (size_t)sr * 768 + sc * 8);
        CP16(vs_b + off, Vp + (size_t)sr * 768 + sc * 8);
        CP_COMMIT();
    }

    // Q fragments for both m-blocks (rows w*32+16*mb+{g,g+8})
    uint32_t qa[2][2][4];
    {
        const uint32_t* q32 = (const uint32_t*)Qp;
#pragma unroll
        for (int mb = 0; mb < 2; mb++) {
            const size_t r0 = (size_t)(l0 + w * 32 + mb * 16 + g) * 768;
            const size_t r1 = r0 + 8 * 768;
#pragma unroll
            for (int s = 0; s < 2; s++)
#pragma unroll
                for (int i = 0; i < 4; i++) {
                    size_t rr = (i & 1) ? r1 : r0;
                    int d = 16 * s + ((i >> 1) ? 8 : 0) + 2 * t;
                    uint32_t pk = __ldg(q32 + ((rr + d) >> 1));
                    __half2 hv = *(__half2*)&pk;
                    qa[mb][s][i] = packh2(__low2float(hv) * scale,
                                          __high2float(hv) * scale);
                }
        }
    }

    float O[2][4][4], Osum[2][4];
#pragma unroll
    for (int mb = 0; mb < 2; mb++)
#pragma unroll
        for (int i = 0; i < 4; i++) {
            Osum[mb][i] = 0.0f;
#pragma unroll
            for (int q = 0; q < 4; q++) O[mb][i][q] = 0.0f;
        }
    const uint32_t ones = (lane < 4) ? 0x3C003C00u : 0u;   // B col 0 = 1

    const int krow = ((lane >> 4) & 1) * 8 + (lane & 7);   // K (non-trans)
    const int kcp  = ((lane >> 3) & 1) * 8;
    const int vrow = ((lane >> 3) & 1) * 8 + (lane & 7);   // V (trans)
    const int vcp  = ((lane >> 4) & 1) * 8;

    for (int kt = 0; kt < 64; kt++) {
        const uint32_t cur = (uint32_t)(kt & 1);
        if (kt < 63) {
            const int c1 = (kt + 1) * 64;
            uint32_t off = (cur ^ 1) * KVB + (sr * PKV + sc * 8) * 2;
            CP16(ks_b + off, Kp + (size_t)(c1 + sr) * 768 + sc * 8);
            CP16(vs_b + off, Vp + (size_t)(c1 + sr) * 768 + sc * 8);
            CP_COMMIT();
            CP_WAIT(1);
        } else {
            CP_WAIT(0);
        }
        __syncthreads();

        const uint32_t kb = ks_b + cur * KVB, vb = vs_b + cur * KVB;

#pragma unroll
        for (int mb = 0; mb < 2; mb++) {
            // S = Q K^T (log2 domain)
            float Cv[8][4];
#pragma unroll
            for (int i = 0; i < 8; i++)
#pragma unroll
                for (int q = 0; q < 4; q++) Cv[i][q] = 0.0f;
#pragma unroll
            for (int s = 0; s < 2; s++)
#pragma unroll
                for (int nbp = 0; nbp < 4; nbp++) {
                    uint32_t b[4];
                    ldsm_x4(b, kb + ((nbp * 16 + krow) * PKV + s * 16 + kcp) * 2);
                    mma16816(Cv[2 * nbp], qa[mb][s], b[0], b[1]);
                    mma16816(Cv[2 * nbp + 1], qa[mb][s], b[2], b[3]);
                }

            // P = 2^S (half2), identity C->A fragment map
            uint32_t P[8][2];
#pragma unroll
            for (int i = 0; i < 8; i++) {
                P[i][0] = ex2h2(packh2(Cv[i][0], Cv[i][1]));
                P[i][1] = ex2h2(packh2(Cv[i][2], Cv[i][3]));
            }

            // O += P V ; Osum += P * ones
#pragma unroll
            for (int s = 0; s < 4; s++) {
                uint32_t a[4] = {P[2 * s][0], P[2 * s][1],
                                 P[2 * s + 1][0], P[2 * s + 1][1]};
#pragma unroll
                for (int dp = 0; dp < 2; dp++) {
                    uint32_t b[4];
                    ldsm_x4t(b, vb + ((16 * s + vrow) * PKV + dp * 16 + vcp) * 2);
                    mma16816(O[mb][2 * dp], a, b[0], b[1]);
                    mma16816(O[mb][2 * dp + 1], a, b[2], b[3]);
                }
                mma16816(Osum[mb], a, ones, ones);
            }
        }
        __syncthreads();
    }

    // Epilogue per m-block
    float* ob = out + ((size_t)(n * CC + h * HD)) * LL;
#pragma unroll
    for (int mb = 0; mb < 2; mb++) {
        float lsum0 = __shfl_sync(0xffffffffu, Osum[mb][0], lane & 28);
        float lsum1 = __shfl_sync(0xffffffffu, Osum[mb][2], lane & 28);
        const float inv0 = 1.0f / lsum0, inv1 = 1.0f / lsum1;
        const int q0 = l0 + w * 32 + mb * 16 + g;
#pragma unroll
        for (int nb2 = 0; nb2 < 4; nb2++) {
            int d = nb2 * 8 + 2 * t;
            ob[(size_t)d * LL + q0]           = O[mb][nb2][0] * inv0;
            ob[(size_t)(d + 1) * LL + q0]     = O[mb][nb2][1] * inv0;
            ob[(size_t)d * LL + q0 + 8]       = O[mb][nb2][2] * inv1;
            ob[(size_t)(d + 1) * LL + q0 + 8] = O[mb][nb2][3] * inv1;
        }
    }
}

// ---------------------------------------------------------------------------
extern "C" void kernel_launch(void* const* d_in, const int* in_sizes, int n_in,
                              void* d_out, int out_size) {
    const float* x = (const float*)d_in[0];   // (4,256,64,64) fp32
    const float* W = (const float*)d_in[1];   // (256,768) fp32
    float* out = (float*)d_out;               // (4,256,64,64) fp32

    static bool attr_set = false;
    if (!attr_set) {
        cudaFuncSetAttribute(qkv_mma, cudaFuncAttributeMaxDynamicSharedMemorySize,
                             (ASZ + 2 * BCH) * 2);
        attr_set = true;
    }

    pe_kernel<<<256, 256>>>();
    w_conv<<<96, 256>>>(W);
    qkv_mma<<<128, 256, (ASZ + 2 * BCH) * 2>>>(x);
    attn_mma<<<dim3(16, NH, NB), 256>>>(out);
}

// round 16
// speedup vs baseline: 3.3628x; 1.0562x over previous
#include <cuda_runtime.h>
#include <cuda_fp16.h>
#include <math.h>
#include <stdint.h>

#define NB 4
#define CC 256
#define LL 4096
#define NH 8
#define HD 32

__device__ float  g_peT[(size_t)CC * LL];          // 4 MB fp32 PE table
__device__ __half g_qkv[(size_t)NB * LL * 768];    // 25 MB fp16 activations
__device__ __half g_Wh[(size_t)CC * 768];          // 384 KB fp16 weights

// ============================ helpers ============================
__device__ __forceinline__ uint32_t smem_u32(const void* p) {
    return (uint32_t)__cvta_generic_to_shared(p);
}
__device__ __forceinline__ void ldsm_x4(uint32_t r[4], uint32_t a) {
    asm volatile("ldmatrix.sync.aligned.m8n8.x4.shared.b16 {%0,%1,%2,%3}, [%4];"
                 : "=r"(r[0]), "=r"(r[1]), "=r"(r[2]), "=r"(r[3]) : "r"(a));
}
__device__ __forceinline__ void ldsm_x4t(uint32_t r[4], uint32_t a) {
    asm volatile("ldmatrix.sync.aligned.m8n8.x4.trans.shared.b16 {%0,%1,%2,%3}, [%4];"
                 : "=r"(r[0]), "=r"(r[1]), "=r"(r[2]), "=r"(r[3]) : "r"(a));
}
// fp32-accum fp16 MMA
__device__ __forceinline__ void mma16816(float c[4], const uint32_t a[4],
                                         uint32_t b0, uint32_t b1) {
    asm volatile(
        "mma.sync.aligned.m16n8k16.row.col.f32.f16.f16.f32 "
        "{%0,%1,%2,%3},{%4,%5,%6,%7},{%8,%9},{%0,%1,%2,%3};"
        : "+f"(c[0]), "+f"(c[1]), "+f"(c[2]), "+f"(c[3])
        : "r"(a[0]), "r"(a[1]), "r"(a[2]), "r"(a[3]), "r"(b0), "r"(b1));
}
// fp16-accum fp16 MMA: D = 2 packed half2 regs (identity layout for ex2.f16x2)
__device__ __forceinline__ void mma16816h(uint32_t c[2], const uint32_t a[4],
                                          uint32_t b0, uint32_t b1) {
    asm volatile(
        "mma.sync.aligned.m16n8k16.row.col.f16.f16.f16.f16 "
        "{%0,%1},{%2,%3,%4,%5},{%6,%7},{%0,%1};"
        : "+r"(c[0]), "+r"(c[1])
        : "r"(a[0]), "r"(a[1]), "r"(a[2]), "r"(a[3]), "r"(b0), "r"(b1));
}
__device__ __forceinline__ uint32_t packh2(float lo, float hi) {   // lo -> low 16 bits
    uint32_t d;
    asm("cvt.rn.f16x2.f32 %0, %1, %2;" : "=r"(d) : "f"(hi), "f"(lo));
    return d;
}
__device__ __forceinline__ uint32_t ex2h2(uint32_t x) {            // 2^x on half2
    uint32_t d;
    asm("ex2.approx.f16x2 %0, %1;" : "=r"(d) : "r"(x));
    return d;
}
__device__ __forceinline__ __half2 u2h(uint32_t u) { return *(__half2*)&u; }
#define CP16(dst, src) \
    asm volatile("cp.async.cg.shared.global [%0], [%1], 16;" :: "r"(dst), "l"(src))
#define CP_COMMIT() asm volatile("cp.async.commit_group;" ::: "memory")
#define CP_WAIT(n)  asm volatile("cp.async.wait_group %0;" :: "n"(n) : "memory")

// ---------------------------------------------------------------------------
// Kernel 0a: positional encoding peT[c][l]; grid (256 channels, 2 halves).
// ---------------------------------------------------------------------------
__global__ void pe_kernel() {
    __shared__ double s_inv;
    __shared__ float s_phase[8];
    const int c = blockIdx.x;
    const int lbase = blockIdx.y * 2048;
    const int tid = threadIdx.x;
    if (tid == 0) s_inv = pow(10000.0, -(double)((c >> 1) * 2) / 256.0);
    __syncthreads();
    if (tid < 8) {
        double a0 = (double)(lbase + tid * 256) * s_inv;
        const double TP = 6.283185307179586476925286766559;
        s_phase[tid] = (float)(a0 - floor(a0 / TP) * TP);
    }
    const float invf = (float)s_inv;
    __syncthreads();
    float* dst = g_peT + (size_t)c * LL + lbase;
    const bool odd = c & 1;
    const float I2P   = 0.15915494309189535f;
    const float P2_HI = 6.2831854820251465f;
    const float P2_LO = -1.7484556e-7f;
#pragma unroll
    for (int j = 0; j < 8; j++) {
        float ang = fmaf((float)tid, invf, s_phase[j]);
        float k = rintf(ang * I2P);
        float r = fmaf(-k, P2_HI, ang);
        r = fmaf(-k, P2_LO, r);
        dst[j * 256 + tid] = odd ? __cosf(r) : __sinf(r);
    }
}

// ---------------------------------------------------------------------------
// Kernel 0b: W fp32 -> fp16
// ---------------------------------------------------------------------------
__global__ void w_conv(const float* __restrict__ W) {
    int i = (blockIdx.x * 256 + threadIdx.x) * 8;
    float4 a = *(const float4*)(W + i);
    float4 b = *(const float4*)(W + i + 4);
    uint4 o;
    o.x = packh2(a.x, a.y); o.y = packh2(a.z, a.w);
    o.z = packh2(b.x, b.y); o.w = packh2(b.z, b.w);
    *(uint4*)((uint32_t*)g_Wh + (i >> 1)) = o;
}

// ---------------------------------------------------------------------------
// Kernel 1: qkv(fp16) = (x^T + PE) @ W_qkv.  A-resident (x read once),
// 6 j-tiles of 128, B double-buffered cp.async, ONE sync per k-chunk.
// ---------------------------------------------------------------------------
#define QP 136
#define ASZ (256 * QP)            /* halves */
#define BCH (32 * QP)             /* halves per B buffer */
__global__ __launch_bounds__(256) void qkv_mma(const float* __restrict__ x) {
    extern __shared__ __half sm[];
    __half* As = sm;              // [k=256][m=128] pitch QP
    __half* Bs = sm + ASZ;        // [2][k=32][n=128] pitch QP

    const int m0 = blockIdx.x * 128;
    const int nb_ = m0 >> 12;
    const int l0 = m0 & (LL - 1);
    const int tid = threadIdx.x, w = tid >> 5, lane = tid & 31;
    const int g = lane >> 2, t = lane & 3;
    const float* xb = x + (size_t)nb_ * CC * LL;

    const uint32_t as_b = smem_u32(As), bs_b = smem_u32(Bs);
    const int stk = tid >> 3, stoff = (tid & 7) * 16;
    const int brow0 = tid >> 4, bch0 = tid & 15;
    const int arow = ((lane >> 4) & 1) * 8 + (lane & 7);
    const int acol = w * 16 + ((lane >> 3) & 1) * 8;
    const int brow = ((lane >> 3) & 1) * 8 + (lane & 7);
    const int bcpar = ((lane >> 4) & 1) * 8;

    // ---- Stage full A (once): x^T + PE -> fp16 ----
#pragma unroll
    for (int kc = 0; kc < 256; kc += 32) {
        const float* xr = xb + (size_t)(kc + stk) * LL + l0 + stoff;
        const float* pr = g_peT + (size_t)(kc + stk) * LL + l0 + stoff;
        uint32_t abuf[8];
#pragma unroll
        for (int j = 0; j < 4; j++) {
            float4 xv = *(const float4*)(xr + 4 * j);
            float4 pv = *(const float4*)(pr + 4 * j);
            abuf[2 * j]     = packh2(xv.x + pv.x, xv.y + pv.y);
            abuf[2 * j + 1] = packh2(xv.z + pv.z, xv.w + pv.w);
        }
        uint32_t* ar = (uint32_t*)(As + (kc + stk) * QP + stoff);
        *(uint4*)ar       = make_uint4(abuf[0], abuf[1], abuf[2], abuf[3]);
        *(uint4*)(ar + 4) = make_uint4(abuf[4], abuf[5], abuf[6], abuf[7]);
    }
    __syncthreads();

    for (int j = 0; j < 6; j++) {
        const int j0 = j * 128;
        {   // prologue: B chunk 0 -> buf 0
            uint32_t d0 = bs_b + ((brow0 * QP + bch0 * 8) << 1);
            const __half* s0 = g_Wh + (size_t)brow0 * 768 + j0 + bch0 * 8;
            CP16(d0, s0);
            CP16(d0 + ((16 * QP) << 1), s0 + 16 * 768);
            CP_COMMIT();
        }
        float Cv[16][4];
#pragma unroll
        for (int i = 0; i < 16; i++)
#pragma unroll
            for (int q = 0; q < 4; q++) Cv[i][q] = 0.0f;

        for (int kc8 = 0; kc8 < 8; kc8++) {
            const uint32_t cur = (uint32_t)(kc8 & 1);
            CP_WAIT(0);
            __syncthreads();
            if (kc8 < 7) {   // issue next chunk AFTER the barrier (single-sync pipeline)
                uint32_t d0 = bs_b + (((cur ^ 1) * BCH + brow0 * QP + bch0 * 8) << 1);
                const __half* s0 = g_Wh + (size_t)((kc8 + 1) * 32 + brow0) * 768 + j0 + bch0 * 8;
                CP16(d0, s0);
                CP16(d0 + ((16 * QP) << 1), s0 + 16 * 768);
                CP_COMMIT();
            }
            const uint32_t bb = bs_b + ((cur * BCH) << 1);
#pragma unroll
            for (int s = 0; s < 2; s++) {
                uint32_t a[4];
                ldsm_x4t(a, as_b + (((kc8 * 32 + 16 * s + arow) * QP + acol) << 1));
#pragma unroll
                for (int nbp = 0; nbp < 8; nbp++) {
                    uint32_t b[4];
                    ldsm_x4t(b, bb + (((16 * s + brow) * QP + nbp * 16 + bcpar) << 1));
                    mma16816(Cv[2 * nbp], a, b[0], b[1]);
                    mma16816(Cv[2 * nbp + 1], a, b[2], b[3]);
                }
            }
        }

        size_t row0 = (size_t)m0 + w * 16 + g;
        uint32_t* q32 = (uint32_t*)g_qkv;
#pragma unroll
        for (int nbk = 0; nbk < 16; nbk++) {
            int col = j0 + nbk * 8 + 2 * t;
            q32[(row0 * 768 + col) >> 1]       = packh2(Cv[nbk][0], Cv[nbk][1]);
            q32[((row0 + 8) * 768 + col) >> 1] = packh2(Cv[nbk][2], Cv[nbk][3]);
        }
        __syncthreads();   // before next j's prologue overwrites buf 0
    }
}

// ---------------------------------------------------------------------------
// Kernel 2: fp16 HMMA flash attention, BQ=256. fp16-accum S MMA (packed half2
// C -> ex2.f16x2 directly, zero cvt), lsum via hadd2 tree (no ones-MMA),
// K/V ldsm shared across both m-blocks, single sync per tile. grid(16,8,4).
// ---------------------------------------------------------------------------
#define PKV 40
#define KVB (64 * PKV * 2)   /* bytes per K/V buffer */
__global__ __launch_bounds__(256, 2) void attn_mma(float* __restrict__ out) {
    __shared__ __half Ks[2][64 * PKV];   // 2 x 5 KB
    __shared__ __half Vs[2][64 * PKV];   // 2 x 5 KB

    const int qt = blockIdx.x, h = blockIdx.y, n = blockIdx.z;
    const int tid = threadIdx.x, w = tid >> 5, lane = tid & 31;
    const int g = lane >> 2, t = lane & 3;
    const __half* bptr = g_qkv + (size_t)n * LL * 768;
    const __half* Qp = bptr + h * HD;
    const __half* Kp = bptr + 256 + h * HD;
    const __half* Vp = bptr + 512 + h * HD;
    const int l0 = qt * 256;
    const float scale = 0.17677669529663688f * 1.4426950408889634f; // 1/sqrt(32)*log2e

    const uint32_t ks_b = smem_u32(Ks), vs_b = smem_u32(Vs);
    const int sr = tid >> 2, sc = tid & 3;

    {   // prologue: tile 0 -> buffer 0
        uint32_t off = (sr * PKV + sc * 8) * 2;
        CP16(ks_b + off, Kp + (size_t)sr * 768 + sc * 8);
        CP16(vs_b + off, Vp + (size_t)sr * 768 + sc * 8);
        CP_COMMIT();
    }

    // Q fragments for both m-blocks
    uint32_t qa[2][2][4];
    {
        const uint32_t* q32 = (const uint32_t*)Qp;
#pragma unroll
        for (int mb = 0; mb < 2; mb++) {
            const size_t r0 = (size_t)(l0 + w * 32 + mb * 16 + g) * 768;
            const size_t r1 = r0 + 8 * 768;
#pragma unroll
            for (int s = 0; s < 2; s++)
#pragma unroll
                for (int i = 0; i < 4; i++) {
                    size_t rr = (i & 1) ? r1 : r0;
                    int d = 16 * s + ((i >> 1) ? 8 : 0) + 2 * t;
                    uint32_t pk = __ldg(q32 + ((rr + d) >> 1));
                    __half2 hv = *(__half2*)&pk;
                    qa[mb][s][i] = packh2(__low2float(hv) * scale,
                                          __high2float(hv) * scale);
                }
        }
    }

    float O[2][4][4];
    float lsum[2][2];   // [mb][row g / g+8]
#pragma unroll
    for (int mb = 0; mb < 2; mb++) {
        lsum[mb][0] = lsum[mb][1] = 0.0f;
#pragma unroll
        for (int i = 0; i < 4; i++)
#pragma unroll
            for (int q = 0; q < 4; q++) O[mb][i][q] = 0.0f;
    }

    const int krow = ((lane >> 4) & 1) * 8 + (lane & 7);   // K (non-trans)
    const int kcp  = ((lane >> 3) & 1) * 8;
    const int vrow = ((lane >> 3) & 1) * 8 + (lane & 7);   // V (trans)
    const int vcp  = ((lane >> 4) & 1) * 8;

    for (int kt = 0; kt < 64; kt++) {
        const uint32_t cur = (uint32_t)(kt & 1);
        CP_WAIT(0);
        __syncthreads();
        if (kt < 63) {   // issue next tile AFTER the barrier (single-sync)
            const int c1 = (kt + 1) * 64;
            uint32_t off = (cur ^ 1) * KVB + (sr * PKV + sc * 8) * 2;
            CP16(ks_b + off, Kp + (size_t)(c1 + sr) * 768 + sc * 8);
            CP16(vs_b + off, Vp + (size_t)(c1 + sr) * 768 + sc * 8);
            CP_COMMIT();
        }

        const uint32_t kb = ks_b + cur * KVB, vb = vs_b + cur * KVB;

        // S = Q K^T (log2 domain), fp16 accumulate; K frag shared across mb
        uint32_t Sh[2][8][2];
#pragma unroll
        for (int mb = 0; mb < 2; mb++)
#pragma unroll
            for (int i = 0; i < 8; i++) Sh[mb][i][0] = Sh[mb][i][1] = 0u;
#pragma unroll
        for (int s = 0; s < 2; s++)
#pragma unroll
            for (int nbp = 0; nbp < 4; nbp++) {
                uint32_t b[4];
                ldsm_x4(b, kb + ((nbp * 16 + krow) * PKV + s * 16 + kcp) * 2);
                mma16816h(Sh[0][2 * nbp],     qa[0][s], b[0], b[1]);
                mma16816h(Sh[0][2 * nbp + 1], qa[0][s], b[2], b[3]);
                mma16816h(Sh[1][2 * nbp],     qa[1][s], b[0], b[1]);
                mma16816h(Sh[1][2 * nbp + 1], qa[1][s], b[2], b[3]);
            }

        // P = 2^S in place (packed half2, identity A-frag layout)
#pragma unroll
        for (int mb = 0; mb < 2; mb++)
#pragma unroll
            for (int i = 0; i < 8; i++) {
                Sh[mb][i][0] = ex2h2(Sh[mb][i][0]);
                Sh[mb][i][1] = ex2h2(Sh[mb][i][1]);
            }

        // O += P V ; V frag shared across mb
#pragma unroll
        for (int s = 0; s < 4; s++) {
            uint32_t a0[4] = {Sh[0][2 * s][0], Sh[0][2 * s][1],
                              Sh[0][2 * s + 1][0], Sh[0][2 * s + 1][1]};
            uint32_t a1[4] = {Sh[1][2 * s][0], Sh[1][2 * s][1],
                              Sh[1][2 * s + 1][0], Sh[1][2 * s + 1][1]};
#pragma unroll
            for (int dp = 0; dp < 2; dp++) {
                uint32_t b[4];
                ldsm_x4t(b, vb + ((16 * s + vrow) * PKV + dp * 16 + vcp) * 2);
                mma16816(O[0][2 * dp],     a0, b[0], b[1]);
                mma16816(O[0][2 * dp + 1], a0, b[2], b[3]);
                mma16816(O[1][2 * dp],     a1, b[0], b[1]);
                mma16816(O[1][2 * dp + 1], a1, b[2], b[3]);
            }
        }

        // lsum: pairwise hadd2 tree over P (same fp16 values as PV numerator)
#pragma unroll
        for (int mb = 0; mb < 2; mb++) {
#pragma unroll
            for (int rw = 0; rw < 2; rw++) {
                __half2 a01 = __hadd2(u2h(Sh[mb][0][rw]), u2h(Sh[mb][1][rw]));
                __half2 a23 = __hadd2(u2h(Sh[mb][2][rw]), u2h(Sh[mb][3][rw]));
                __half2 a45 = __hadd2(u2h(Sh[mb][4][rw]), u2h(Sh[mb][5][rw]));
                __half2 a67 = __hadd2(u2h(Sh[mb][6][rw]), u2h(Sh[mb][7][rw]));
                __half2 r = __hadd2(__hadd2(a01, a23), __hadd2(a45, a67));
                float2 f = __half22float2(r);
                lsum[mb][rw] += f.x + f.y;
            }
        }
    }

    // Epilogue
    float* ob = out + ((size_t)(n * CC + h * HD)) * LL;
#pragma unroll
    for (int mb = 0; mb < 2; mb++) {
        float l0s = lsum[mb][0], l1s = lsum[mb][1];
        l0s += __shfl_xor_sync(0xffffffffu, l0s, 1);
        l0s += __shfl_xor_sync(0xffffffffu, l0s, 2);
        l1s += __shfl_xor_sync(0xffffffffu, l1s, 1);
        l1s += __shfl_xor_sync(0xffffffffu, l1s, 2);
        const float inv0 = 1.0f / l0s, inv1 = 1.0f / l1s;
        const int q0 = l0 + w * 32 + mb * 16 + g;
#pragma unroll
        for (int nb2 = 0; nb2 < 4; nb2++) {
            int d = nb2 * 8 + 2 * t;
            ob[(size_t)d * LL + q0]           = O[mb][nb2][0] * inv0;
            ob[(size_t)(d + 1) * LL + q0]     = O[mb][nb2][1] * inv0;
            ob[(size_t)d * LL + q0 + 8]       = O[mb][nb2][2] * inv1;
            ob[(size_t)(d + 1) * LL + q0 + 8] = O[mb][nb2][3] * inv1;
        }
    }
}

// ---------------------------------------------------------------------------
extern "C" void kernel_launch(void* const* d_in, const int* in_sizes, int n_in,
                              void* d_out, int out_size) {
    const float* x = (const float*)d_in[0];   // (4,256,64,64) fp32
    const float* W = (const float*)d_in[1];   // (256,768) fp32
    float* out = (float*)d_out;               // (4,256,64,64) fp32

    static bool attr_set = false;
    if (!attr_set) {
        cudaFuncSetAttribute(qkv_mma, cudaFuncAttributeMaxDynamicSharedMemorySize,
                             (ASZ + 2 * BCH) * 2);
        attr_set = true;
    }

    pe_kernel<<<dim3(256, 2), 256>>>();
    w_conv<<<96, 256>>>(W);
    qkv_mma<<<128, 256, (ASZ + 2 * BCH) * 2>>>(x);
    attn_mma<<<dim3(16, NH, NB), 256>>>(out);
}

// round 17
// speedup vs baseline: 3.4265x; 1.0190x over previous
#include <cuda_runtime.h>
#include <cuda_fp16.h>
#include <math.h>
#include <stdint.h>

#define NB 4
#define CC 256
#define LL 4096
#define NH 8
#define HD 32

__device__ float  g_peT[(size_t)CC * LL];          // 4 MB fp32 PE table
__device__ __half g_qkv[(size_t)NB * LL * 768];    // 25 MB fp16 activations
__device__ __half g_Wh[(size_t)CC * 768];          // 384 KB fp16 weights

// ============================ helpers ============================
__device__ __forceinline__ uint32_t smem_u32(const void* p) {
    return (uint32_t)__cvta_generic_to_shared(p);
}
__device__ __forceinline__ void ldsm_x4(uint32_t r[4], uint32_t a) {
    asm volatile("ldmatrix.sync.aligned.m8n8.x4.shared.b16 {%0,%1,%2,%3}, [%4];"
                 : "=r"(r[0]), "=r"(r[1]), "=r"(r[2]), "=r"(r[3]) : "r"(a));
}
__device__ __forceinline__ void ldsm_x4t(uint32_t r[4], uint32_t a) {
    asm volatile("ldmatrix.sync.aligned.m8n8.x4.trans.shared.b16 {%0,%1,%2,%3}, [%4];"
                 : "=r"(r[0]), "=r"(r[1]), "=r"(r[2]), "=r"(r[3]) : "r"(a));
}
// fp32-accum fp16 MMA
__device__ __forceinline__ void mma16816(float c[4], const uint32_t a[4],
                                         uint32_t b0, uint32_t b1) {
    asm volatile(
        "mma.sync.aligned.m16n8k16.row.col.f32.f16.f16.f32 "
        "{%0,%1,%2,%3},{%4,%5,%6,%7},{%8,%9},{%0,%1,%2,%3};"
        : "+f"(c[0]), "+f"(c[1]), "+f"(c[2]), "+f"(c[3])
        : "r"(a[0]), "r"(a[1]), "r"(a[2]), "r"(a[3]), "r"(b0), "r"(b1));
}
// fp16-accum fp16 MMA: D = 2 packed half2 regs (identity layout for ex2.f16x2)
__device__ __forceinline__ void mma16816h(uint32_t c[2], const uint32_t a[4],
                                          uint32_t b0, uint32_t b1) {
    asm volatile(
        "mma.sync.aligned.m16n8k16.row.col.f16.f16.f16.f16 "
        "{%0,%1},{%2,%3,%4,%5},{%6,%7},{%0,%1};"
        : "+r"(c[0]), "+r"(c[1])
        : "r"(a[0]), "r"(a[1]), "r"(a[2]), "r"(a[3]), "r"(b0), "r"(b1));
}
__device__ __forceinline__ uint32_t packh2(float lo, float hi) {   // lo -> low 16 bits
    uint32_t d;
    asm("cvt.rn.f16x2.f32 %0, %1, %2;" : "=r"(d) : "f"(hi), "f"(lo));
    return d;
}
__device__ __forceinline__ uint32_t ex2h2(uint32_t x) {            // 2^x on half2
    uint32_t d;
    asm("ex2.approx.f16x2 %0, %1;" : "=r"(d) : "r"(x));
    return d;
}
__device__ __forceinline__ __half2 u2h(uint32_t u) { return *(__half2*)&u; }
#define CP16(dst, src) \
    asm volatile("cp.async.cg.shared.global [%0], [%1], 16;" :: "r"(dst), "l"(src))
#define CP_COMMIT() asm volatile("cp.async.commit_group;" ::: "memory")
#define CP_WAIT(n)  asm volatile("cp.async.wait_group %0;" :: "n"(n) : "memory")

// ---------------------------------------------------------------------------
// Kernel 0a: positional encoding peT[c][l]; grid (256 channels, 2 halves).
// ---------------------------------------------------------------------------
__global__ void pe_kernel() {
    __shared__ double s_inv;
    __shared__ float s_phase[8];
    const int c = blockIdx.x;
    const int lbase = blockIdx.y * 2048;
    const int tid = threadIdx.x;
    if (tid == 0) s_inv = pow(10000.0, -(double)((c >> 1) * 2) / 256.0);
    __syncthreads();
    if (tid < 8) {
        double a0 = (double)(lbase + tid * 256) * s_inv;
        const double TP = 6.283185307179586476925286766559;
        s_phase[tid] = (float)(a0 - floor(a0 / TP) * TP);
    }
    const float invf = (float)s_inv;
    __syncthreads();
    float* dst = g_peT + (size_t)c * LL + lbase;
    const bool odd = c & 1;
    const float I2P   = 0.15915494309189535f;
    const float P2_HI = 6.2831854820251465f;
    const float P2_LO = -1.7484556e-7f;
#pragma unroll
    for (int j = 0; j < 8; j++) {
        float ang = fmaf((float)tid, invf, s_phase[j]);
        float k = rintf(ang * I2P);
        float r = fmaf(-k, P2_HI, ang);
        r = fmaf(-k, P2_LO, r);
        dst[j * 256 + tid] = odd ? __cosf(r) : __sinf(r);
    }
}

// ---------------------------------------------------------------------------
// Kernel 0b: W fp32 -> fp16
// ---------------------------------------------------------------------------
__global__ void w_conv(const float* __restrict__ W) {
    int i = (blockIdx.x * 256 + threadIdx.x) * 8;
    float4 a = *(const float4*)(W + i);
    float4 b = *(const float4*)(W + i + 4);
    uint4 o;
    o.x = packh2(a.x, a.y); o.y = packh2(a.z, a.w);
    o.z = packh2(b.x, b.y); o.w = packh2(b.z, b.w);
    *(uint4*)((uint32_t*)g_Wh + (i >> 1)) = o;
}

// ---------------------------------------------------------------------------
// Kernel 1: qkv(fp16) = (x^T + PE) @ W_qkv.  A-resident (x read once),
// 6 j-tiles of 128, B double-buffered cp.async, one sync per k-chunk.
// ---------------------------------------------------------------------------
#define QP 136
#define ASZ (256 * QP)            /* halves */
#define BCH (32 * QP)             /* halves per B buffer */
__global__ __launch_bounds__(256) void qkv_mma(const float* __restrict__ x) {
    extern __shared__ __half sm[];
    __half* As = sm;              // [k=256][m=128] pitch QP
    __half* Bs = sm + ASZ;        // [2][k=32][n=128] pitch QP

    const int m0 = blockIdx.x * 128;
    const int nb_ = m0 >> 12;
    const int l0 = m0 & (LL - 1);
    const int tid = threadIdx.x, w = tid >> 5, lane = tid & 31;
    const int g = lane >> 2, t = lane & 3;
    const float* xb = x + (size_t)nb_ * CC * LL;

    const uint32_t as_b = smem_u32(As), bs_b = smem_u32(Bs);
    const int stk = tid >> 3, stoff = (tid & 7) * 16;
    const int brow0 = tid >> 4, bch0 = tid & 15;
    const int arow = ((lane >> 4) & 1) * 8 + (lane & 7);
    const int acol = w * 16 + ((lane >> 3) & 1) * 8;
    const int brow = ((lane >> 3) & 1) * 8 + (lane & 7);
    const int bcpar = ((lane >> 4) & 1) * 8;

    // ---- Stage full A (once): x^T + PE -> fp16 ----
#pragma unroll
    for (int kc = 0; kc < 256; kc += 32) {
        const float* xr = xb + (size_t)(kc + stk) * LL + l0 + stoff;
        const float* pr = g_peT + (size_t)(kc + stk) * LL + l0 + stoff;
        uint32_t abuf[8];
#pragma unroll
        for (int j = 0; j < 4; j++) {
            float4 xv = *(const float4*)(xr + 4 * j);
            float4 pv = *(const float4*)(pr + 4 * j);
            abuf[2 * j]     = packh2(xv.x + pv.x, xv.y + pv.y);
            abuf[2 * j + 1] = packh2(xv.z + pv.z, xv.w + pv.w);
        }
        uint32_t* ar = (uint32_t*)(As + (kc + stk) * QP + stoff);
        *(uint4*)ar       = make_uint4(abuf[0], abuf[1], abuf[2], abuf[3]);
        *(uint4*)(ar + 4) = make_uint4(abuf[4], abuf[5], abuf[6], abuf[7]);
    }
    __syncthreads();

    for (int j = 0; j < 6; j++) {
        const int j0 = j * 128;
        {   // prologue: B chunk 0 -> buf 0
            uint32_t d0 = bs_b + ((brow0 * QP + bch0 * 8) << 1);
            const __half* s0 = g_Wh + (size_t)brow0 * 768 + j0 + bch0 * 8;
            CP16(d0, s0);
            CP16(d0 + ((16 * QP) << 1), s0 + 16 * 768);
            CP_COMMIT();
        }
        float Cv[16][4];
#pragma unroll
        for (int i = 0; i < 16; i++)
#pragma unroll
            for (int q = 0; q < 4; q++) Cv[i][q] = 0.0f;

        for (int kc8 = 0; kc8 < 8; kc8++) {
            const uint32_t cur = (uint32_t)(kc8 & 1);
            CP_WAIT(0);
            __syncthreads();
            if (kc8 < 7) {
                uint32_t d0 = bs_b + (((cur ^ 1) * BCH + brow0 * QP + bch0 * 8) << 1);
                const __half* s0 = g_Wh + (size_t)((kc8 + 1) * 32 + brow0) * 768 + j0 + bch0 * 8;
                CP16(d0, s0);
                CP16(d0 + ((16 * QP) << 1), s0 + 16 * 768);
                CP_COMMIT();
            }
            const uint32_t bb = bs_b + ((cur * BCH) << 1);
#pragma unroll
            for (int s = 0; s < 2; s++) {
                uint32_t a[4];
                ldsm_x4t(a, as_b + (((kc8 * 32 + 16 * s + arow) * QP + acol) << 1));
#pragma unroll
                for (int nbp = 0; nbp < 8; nbp++) {
                    uint32_t b[4];
                    ldsm_x4t(b, bb + (((16 * s + brow) * QP + nbp * 16 + bcpar) << 1));
                    mma16816(Cv[2 * nbp], a, b[0], b[1]);
                    mma16816(Cv[2 * nbp + 1], a, b[2], b[3]);
                }
            }
        }

        size_t row0 = (size_t)m0 + w * 16 + g;
        uint32_t* q32 = (uint32_t*)g_qkv;
#pragma unroll
        for (int nbk = 0; nbk < 16; nbk++) {
            int col = j0 + nbk * 8 + 2 * t;
            q32[(row0 * 768 + col) >> 1]       = packh2(Cv[nbk][0], Cv[nbk][1]);
            q32[((row0 + 8) * 768 + col) >> 1] = packh2(Cv[nbk][2], Cv[nbk][3]);
        }
        __syncthreads();
    }
}

// ---------------------------------------------------------------------------
// Kernel 2: fp16 HMMA flash attention, BQ=256. Skewed m-block pipeline:
// exp(mb0) hidden under S-MMA(mb1); exp(mb1) hidden under PV(mb0).
// grid(16,8,4), 256 thr, occ 2.
// ---------------------------------------------------------------------------
#define PKV 40
#define KVB (64 * PKV * 2)   /* bytes per K/V buffer */
__global__ __launch_bounds__(256, 2) void attn_mma(float* __restrict__ out) {
    __shared__ __half Ks[2][64 * PKV];   // 2 x 5 KB
    __shared__ __half Vs[2][64 * PKV];   // 2 x 5 KB

    const int qt = blockIdx.x, h = blockIdx.y, n = blockIdx.z;
    const int tid = threadIdx.x, w = tid >> 5, lane = tid & 31;
    const int g = lane >> 2, t = lane & 3;
    const __half* bptr = g_qkv + (size_t)n * LL * 768;
    const __half* Qp = bptr + h * HD;
    const __half* Kp = bptr + 256 + h * HD;
    const __half* Vp = bptr + 512 + h * HD;
    const int l0 = qt * 256;
    const float scale = 0.17677669529663688f * 1.4426950408889634f; // 1/sqrt(32)*log2e

    const uint32_t ks_b = smem_u32(Ks), vs_b = smem_u32(Vs);
    const int sr = tid >> 2, sc = tid & 3;

    {   // prologue: tile 0 -> buffer 0
        uint32_t off = (sr * PKV + sc * 8) * 2;
        CP16(ks_b + off, Kp + (size_t)sr * 768 + sc * 8);
        CP16(vs_b + off, Vp + (size_t)sr * 768 + sc * 8);
        CP_COMMIT();
    }

    // Q fragments for both m-blocks
    uint32_t qa[2][2][4];
    {
        const uint32_t* q32 = (const uint32_t*)Qp;
#pragma unroll
        for (int mb = 0; mb < 2; mb++) {
            const size_t r0 = (size_t)(l0 + w * 32 + mb * 16 + g) * 768;
            const size_t r1 = r0 + 8 * 768;
#pragma unroll
            for (int s = 0; s < 2; s++)
#pragma unroll
                for (int i = 0; i < 4; i++) {
                    size_t rr = (i & 1) ? r1 : r0;
                    int d = 16 * s + ((i >> 1) ? 8 : 0) + 2 * t;
                    uint32_t pk = __ldg(q32 + ((rr + d) >> 1));
                    __half2 hv = *(__half2*)&pk;
                    qa[mb][s][i] = packh2(__low2float(hv) * scale,
                                          __high2float(hv) * scale);
                }
        }
    }

    float O[2][4][4];
    float lsum[2][2];
#pragma unroll
    for (int mb = 0; mb < 2; mb++) {
        lsum[mb][0] = lsum[mb][1] = 0.0f;
#pragma unroll
        for (int i = 0; i < 4; i++)
#pragma unroll
            for (int q = 0; q < 4; q++) O[mb][i][q] = 0.0f;
    }

    const int krow = ((lane >> 4) & 1) * 8 + (lane & 7);
    const int kcp  = ((lane >> 3) & 1) * 8;
    const int vrow = ((lane >> 3) & 1) * 8 + (lane & 7);
    const int vcp  = ((lane >> 4) & 1) * 8;

    for (int kt = 0; kt < 64; kt++) {
        const uint32_t cur = (uint32_t)(kt & 1);
        CP_WAIT(0);
        __syncthreads();
        if (kt < 63) {
            const int c1 = (kt + 1) * 64;
            uint32_t off = (cur ^ 1) * KVB + (sr * PKV + sc * 8) * 2;
            CP16(ks_b + off, Kp + (size_t)(c1 + sr) * 768 + sc * 8);
            CP16(vs_b + off, Vp + (size_t)(c1 + sr) * 768 + sc * 8);
            CP_COMMIT();
        }

        const uint32_t kb = ks_b + cur * KVB, vb = vs_b + cur * KVB;

        // Phase 1a: hoist K frags, S-MMA(mb0)
        uint32_t kf[2][4][4];
#pragma unroll
        for (int s = 0; s < 2; s++)
#pragma unroll
            for (int nbp = 0; nbp < 4; nbp++)
                ldsm_x4(kf[s][nbp], kb + ((nbp * 16 + krow) * PKV + s * 16 + kcp) * 2);

        uint32_t Sh0[8][2], Sh1[8][2];
#pragma unroll
        for (int i = 0; i < 8; i++) { Sh0[i][0] = Sh0[i][1] = 0u; }
#pragma unroll
        for (int s = 0; s < 2; s++)
#pragma unroll
            for (int nbp = 0; nbp < 4; nbp++) {
                mma16816h(Sh0[2 * nbp],     qa[0][s], kf[s][nbp][0], kf[s][nbp][1]);
                mma16816h(Sh0[2 * nbp + 1], qa[0][s], kf[s][nbp][2], kf[s][nbp][3]);
            }

        // Phase 1b: S-MMA(mb1) interleaved with exp(mb0)
#pragma unroll
        for (int i = 0; i < 8; i++) { Sh1[i][0] = Sh1[i][1] = 0u; }
#pragma unroll
        for (int nbp = 0; nbp < 4; nbp++) {
            mma16816h(Sh1[2 * nbp],     qa[1][0], kf[0][nbp][0], kf[0][nbp][1]);
            mma16816h(Sh1[2 * nbp + 1], qa[1][0], kf[0][nbp][2], kf[0][nbp][3]);
            Sh0[2 * nbp][0]     = ex2h2(Sh0[2 * nbp][0]);
            Sh0[2 * nbp][1]     = ex2h2(Sh0[2 * nbp][1]);
            mma16816h(Sh1[2 * nbp],     qa[1][1], kf[1][nbp][0], kf[1][nbp][1]);
            mma16816h(Sh1[2 * nbp + 1], qa[1][1], kf[1][nbp][2], kf[1][nbp][3]);
            Sh0[2 * nbp + 1][0] = ex2h2(Sh0[2 * nbp + 1][0]);
            Sh0[2 * nbp + 1][1] = ex2h2(Sh0[2 * nbp + 1][1]);
        }

        // Phase 2: PV(mb0) interleaved with exp(mb1) + lsum0
        __half2 lh0[2] = {__float2half2_rn(0.0f), __float2half2_rn(0.0f)};
        __half2 lh1[2] = {__float2half2_rn(0.0f), __float2half2_rn(0.0f)};
#pragma unroll
        for (int s = 0; s < 4; s++) {
            uint32_t a0[4] = {Sh0[2 * s][0], Sh0[2 * s][1],
                              Sh0[2 * s + 1][0], Sh0[2 * s + 1][1]};
            uint32_t b0[4], b1[4];
            ldsm_x4t(b0, vb + ((16 * s + vrow) * PKV + vcp) * 2);
            ldsm_x4t(b1, vb + ((16 * s + vrow) * PKV + 16 + vcp) * 2);
            mma16816(O[0][0], a0, b0[0], b0[1]);
            Sh1[2 * s][0]     = ex2h2(Sh1[2 * s][0]);
            Sh1[2 * s][1]     = ex2h2(Sh1[2 * s][1]);
            mma16816(O[0][1], a0, b0[2], b0[3]);
            Sh1[2 * s + 1][0] = ex2h2(Sh1[2 * s + 1][0]);
            Sh1[2 * s + 1][1] = ex2h2(Sh1[2 * s + 1][1]);
            mma16816(O[0][2], a0, b1[0], b1[1]);
            mma16816(O[0][3], a0, b1[2], b1[3]);
            lh0[0] = __hadd2(lh0[0], __hadd2(u2h(a0[0]), u2h(a0[2])));
            lh0[1] = __hadd2(lh0[1], __hadd2(u2h(a0[1]), u2h(a0[3])));
        }

        // Phase 3: PV(mb1) + lsum1
#pragma unroll
        for (int s = 0; s < 4; s++) {
            uint32_t a1[4] = {Sh1[2 * s][0], Sh1[2 * s][1],
                              Sh1[2 * s + 1][0], Sh1[2 * s + 1][1]};
            uint32_t b0[4], b1[4];
            ldsm_x4t(b0, vb + ((16 * s + vrow) * PKV + vcp) * 2);
            ldsm_x4t(b1, vb + ((16 * s + vrow) * PKV + 16 + vcp) * 2);
            mma16816(O[1][0], a1, b0[0], b0[1]);
            mma16816(O[1][1], a1, b0[2], b0[3]);
            mma16816(O[1][2], a1, b1[0], b1[1]);
            mma16816(O[1][3], a1, b1[2], b1[3]);
            lh1[0] = __hadd2(lh1[0], __hadd2(u2h(a1[0]), u2h(a1[2])));
            lh1[1] = __hadd2(lh1[1], __hadd2(u2h(a1[1]), u2h(a1[3])));
        }
        {
            float2 f0 = __half22float2(lh0[0]), f1 = __half22float2(lh0[1]);
            lsum[0][0] += f0.x + f0.y;
            lsum[0][1] += f1.x + f1.y;
            float2 g0 = __half22float2(lh1[0]), g1 = __half22float2(lh1[1]);
            lsum[1][0] += g0.x + g0.y;
            lsum[1][1] += g1.x + g1.y;
        }
    }

    // Epilogue
    float* ob = out + ((size_t)(n * CC + h * HD)) * LL;
#pragma unroll
    for (int mb = 0; mb < 2; mb++) {
        float l0s = lsum[mb][0], l1s = lsum[mb][1];
        l0s += __shfl_xor_sync(0xffffffffu, l0s, 1);
        l0s += __shfl_xor_sync(0xffffffffu, l0s, 2);
        l1s += __shfl_xor_sync(0xffffffffu, l1s, 1);
        l1s += __shfl_xor_sync(0xffffffffu, l1s, 2);
        const float inv0 = 1.0f / l0s, inv1 = 1.0f / l1s;
        const int q0 = l0 + w * 32 + mb * 16 + g;
#pragma unroll
        for (int nb2 = 0; nb2 < 4; nb2++) {
            int d = nb2 * 8 + 2 * t;
            ob[(size_t)d * LL + q0]           = O[mb][nb2][0] * inv0;
            ob[(size_t)(d + 1) * LL + q0]     = O[mb][nb2][1] * inv0;
            ob[(size_t)d * LL + q0 + 8]       = O[mb][nb2][2] * inv1;
            ob[(size_t)(d + 1) * LL + q0 + 8] = O[mb][nb2][3] * inv1;
        }
    }
}

// ---------------------------------------------------------------------------
extern "C" void kernel_launch(void* const* d_in, const int* in_sizes, int n_in,
                              void* d_out, int out_size) {
    const float* x = (const float*)d_in[0];   // (4,256,64,64) fp32
    const float* W = (const float*)d_in[1];   // (256,768) fp32
    float* out = (float*)d_out;               // (4,256,64,64) fp32

    static bool attr_set = false;
    if (!attr_set) {
        cudaFuncSetAttribute(qkv_mma, cudaFuncAttributeMaxDynamicSharedMemorySize,
                             (ASZ + 2 * BCH) * 2);
        attr_set = true;
    }

    pe_kernel<<<dim3(256, 2), 256>>>();
    w_conv<<<96, 256>>>(W);
    qkv_mma<<<128, 256, (ASZ + 2 * BCH) * 2>>>(x);
    attn_mma<<<dim3(16, NH, NB), 256>>>(out);
}